// round 2
// baseline (speedup 1.0000x reference)
#include <cuda_runtime.h>
#include <cuda_bf16.h>
#include <cstdint>

typedef __nv_bfloat16 bf16;

#define NB 32      // batch
#define TT 64      // T
#define NSTEP 63   // T-1
#define EE 512
#define HH 1024
#define VV 32000

// ---------------- scratch (static device arrays; zero-initialized at load) ----
__device__ __align__(16) bf16 g_W0[4096 * 2560];   // [Wih0 | Whh0] rows=4096
__device__ __align__(16) bf16 g_W1[4096 * 2048];   // [Wih1 | Whh1]
__device__ __align__(16) bf16 g_Wa[1024 * 1024];
__device__ __align__(16) bf16 g_Wl[1024 * 2048];
__device__ __align__(16) bf16 g_Wg[32000 * 1024];
__device__ __align__(16) bf16 g_eseq[NSTEP * NB * EE];   // [t][b][c]
__device__ __align__(16) bf16 g_outs[66 * NB * HH];      // slot0 = zeros (never written), slot 1+t = out_t, slots 64..65 pad (zeros)
__device__ float g_b0[4096];
__device__ float g_b1[4096];
__device__ float g_gates[NB * 4096];
__device__ __align__(16) bf16 g_h0[NB * HH];
__device__ __align__(16) bf16 g_h1[NB * HH];
__device__ float g_c0[NB * HH];
__device__ float g_c1[NB * HH];
__device__ float g_q[NB * HH];
__device__ __align__(16) bf16 g_ctx[NB * HH];

// ---------------- small helpers -------------------------------------------
__device__ __forceinline__ uint32_t smem_u32(const void* p) {
    return (uint32_t)__cvta_generic_to_shared(p);
}
__device__ __forceinline__ void ldsm4(uint32_t addr, uint32_t& r0, uint32_t& r1,
                                      uint32_t& r2, uint32_t& r3) {
    asm volatile("ldmatrix.sync.aligned.m8n8.x4.shared.b16 {%0,%1,%2,%3}, [%4];"
                 : "=r"(r0), "=r"(r1), "=r"(r2), "=r"(r3) : "r"(addr));
}
__device__ __forceinline__ void mma16816(float* c, uint32_t a0, uint32_t a1,
                                         uint32_t a2, uint32_t a3,
                                         uint32_t b0, uint32_t b1) {
    asm volatile(
        "mma.sync.aligned.m16n8k16.row.col.f32.bf16.bf16.f32 "
        "{%0,%1,%2,%3},{%4,%5,%6,%7},{%8,%9},{%0,%1,%2,%3};"
        : "+f"(c[0]), "+f"(c[1]), "+f"(c[2]), "+f"(c[3])
        : "r"(a0), "r"(a1), "r"(a2), "r"(a3), "r"(b0), "r"(b1));
}
__device__ __forceinline__ float sigmoidf_(float x) { return 1.f / (1.f + expf(-x)); }

// ---------------- conversion kernels --------------------------------------
__global__ void k_cvt(bf16* dst, const float* src, int n) {
    int i = blockIdx.x * blockDim.x + threadIdx.x;
    if (i < n) dst[i] = __float2bfloat16(src[i]);
}
__global__ void k_cvt_pair(bf16* dst, const float* A, int wA, const float* Bm, int wB, int rows) {
    int w = wA + wB;
    int i = blockIdx.x * blockDim.x + threadIdx.x;
    if (i < rows * w) {
        int r = i / w, c = i % w;
        float v = (c < wA) ? A[(size_t)r * wA + c] : Bm[(size_t)r * wB + (c - wA)];
        dst[i] = __float2bfloat16(v);
    }
}
__global__ void k_addb(float* dst, const float* a, const float* b, int n) {
    int i = blockIdx.x * blockDim.x + threadIdx.x;
    if (i < n) dst[i] = a[i] + b[i];
}
__global__ void k_embed(bf16* eseq, const int* x, const float* emb) {
    int i = blockIdx.x * blockDim.x + threadIdx.x;   // over NSTEP*NB*EE
    if (i < NSTEP * NB * EE) {
        int c = i & (EE - 1);
        int bt = i >> 9;          // EE = 512
        int b = bt & (NB - 1);
        int t = bt >> 5;          // NB = 32
        int tok = x[b * TT + t];
        eseq[i] = __float2bfloat16(emb[(size_t)tok * EE + c]);
    }
}
__global__ void k_init(const float* h0, const float* c0) {
    int i = blockIdx.x * blockDim.x + threadIdx.x;
    if (i < NB * HH) {
        g_h0[i] = __float2bfloat16(h0[i]);
        g_h1[i] = __float2bfloat16(h0[NB * HH + i]);
        g_c0[i] = c0[i];
        g_c1[i] = c0[NB * HH + i];
    }
}

// ---------------- step GEMM: C[32,N] = A[32,K] @ W[N,K]^T + bias -----------
// A is split in up to 3 segments along K (boundaries k1, k2; multiples of 32).
// mode 0: store fp32 to Cf.  mode 1: store tanh() as bf16 to Cb.
__global__ void __launch_bounds__(128) k_gemm_step(
    const bf16* __restrict__ A0, int st0,
    const bf16* __restrict__ A1, int st1,
    const bf16* __restrict__ A2, int st2,
    int k1, int k2, int K,
    const bf16* __restrict__ W, const float* __restrict__ bias, int N,
    float* __restrict__ Cf, bf16* __restrict__ Cb, int mode)
{
    __shared__ __align__(16) bf16 As[32 * 40];
    __shared__ __align__(16) bf16 Bs[128 * 40];
    const int tid = threadIdx.x;
    const int warp = tid >> 5, lane = tid & 31;
    const int nblk = blockIdx.x * 128;

    float acc[2][4][4];
#pragma unroll
    for (int a = 0; a < 2; a++)
#pragma unroll
        for (int b = 0; b < 4; b++)
#pragma unroll
            for (int c = 0; c < 4; c++) acc[a][b][c] = 0.f;

    const int sub = lane >> 3, ri = lane & 7;

    for (int kb = 0; kb < K; kb += 32) {
        const bf16* Ab; int as, ko;
        if (kb < k1)      { Ab = A0; as = st0; ko = kb; }
        else if (kb < k2) { Ab = A1; as = st1; ko = kb - k1; }
        else              { Ab = A2; as = st2; ko = kb - k2; }
        __syncthreads();
#pragma unroll
        for (int i = 0; i < 5; i++) {
            int v = tid + i * 128;
            if (v < 128) {
                int m = v >> 2, cv = v & 3;
                uint4 d = *(const uint4*)(Ab + (size_t)m * as + ko + cv * 8);
                *(uint4*)&As[m * 40 + cv * 8] = d;
            } else {
                int u = v - 128;
                int n = u >> 2, cv = u & 3;
                uint4 d = *(const uint4*)(W + (size_t)(nblk + n) * K + kb + cv * 8);
                *(uint4*)&Bs[n * 40 + cv * 8] = d;
            }
        }
        __syncthreads();
#pragma unroll
        for (int kk = 0; kk < 32; kk += 16) {
            uint32_t a[2][4], b[4][2];
#pragma unroll
            for (int mt = 0; mt < 2; mt++) {
                int row = mt * 16 + (sub & 1) * 8 + ri;
                int col = kk + (sub >> 1) * 8;
                ldsm4(smem_u32(&As[row * 40 + col]), a[mt][0], a[mt][1], a[mt][2], a[mt][3]);
            }
#pragma unroll
            for (int ntp = 0; ntp < 2; ntp++) {
                int row = warp * 32 + ntp * 16 + (sub >> 1) * 8 + ri;
                int col = kk + (sub & 1) * 8;
                ldsm4(smem_u32(&Bs[row * 40 + col]),
                      b[ntp * 2][0], b[ntp * 2][1], b[ntp * 2 + 1][0], b[ntp * 2 + 1][1]);
            }
#pragma unroll
            for (int mt = 0; mt < 2; mt++)
#pragma unroll
                for (int nt = 0; nt < 4; nt++)
                    mma16816(acc[mt][nt], a[mt][0], a[mt][1], a[mt][2], a[mt][3],
                             b[nt][0], b[nt][1]);
        }
    }

    const int r0 = lane >> 2, c0 = (lane & 3) * 2;
#pragma unroll
    for (int mt = 0; mt < 2; mt++) {
#pragma unroll
        for (int nt = 0; nt < 4; nt++) {
            int m = mt * 16 + r0;
            int n = nblk + warp * 32 + nt * 8 + c0;
            float bv0 = bias[n], bv1 = bias[n + 1];
            float v00 = acc[mt][nt][0] + bv0;
            float v01 = acc[mt][nt][1] + bv1;
            float v10 = acc[mt][nt][2] + bv0;
            float v11 = acc[mt][nt][3] + bv1;
            if (mode == 0) {
                Cf[(size_t)m * N + n]           = v00;
                Cf[(size_t)m * N + n + 1]       = v01;
                Cf[(size_t)(m + 8) * N + n]     = v10;
                Cf[(size_t)(m + 8) * N + n + 1] = v11;
            } else {
                Cb[(size_t)m * N + n]           = __float2bfloat16(tanhf(v00));
                Cb[(size_t)m * N + n + 1]       = __float2bfloat16(tanhf(v01));
                Cb[(size_t)(m + 8) * N + n]     = __float2bfloat16(tanhf(v10));
                Cb[(size_t)(m + 8) * N + n + 1] = __float2bfloat16(tanhf(v11));
            }
        }
    }
}

// ---------------- LSTM cell elementwise ------------------------------------
__global__ void k_cell(const float* __restrict__ gates, float* __restrict__ c,
                       bf16* __restrict__ h) {
    int i = blockIdx.x * blockDim.x + threadIdx.x;   // NB*HH
    if (i < NB * HH) {
        int b = i >> 10, u = i & (HH - 1);
        const float* g = gates + b * 4096;
        float ig = g[u], fg = g[HH + u], gg = g[2 * HH + u], og = g[3 * HH + u];
        float cn = sigmoidf_(fg) * c[i] + sigmoidf_(ig) * tanhf(gg);
        c[i] = cn;
        h[i] = __float2bfloat16(sigmoidf_(og) * tanhf(cn));
    }
}

// ---------------- attention (per-batch block) -------------------------------
__global__ void __launch_bounds__(256) k_attn(const float* __restrict__ q,
                                              const float* __restrict__ x_enc,
                                              bf16* __restrict__ ctx) {
    int b = blockIdx.x, tid = threadIdx.x;
    __shared__ float qs[HH];
    __shared__ float sc[64];
    for (int i = tid; i < HH; i += 256) qs[i] = q[b * HH + i];
    __syncthreads();
    int warp = tid >> 5, lane = tid & 31;
    const float* xb = x_enc + (size_t)b * 64 * HH;
#pragma unroll
    for (int jj = 0; jj < 8; jj++) {
        int j = warp * 8 + jj;
        const float* xr = xb + (size_t)j * HH;
        float s = 0.f;
        for (int cidx = lane; cidx < HH; cidx += 32) s += qs[cidx] * xr[cidx];
#pragma unroll
        for (int o = 16; o; o >>= 1) s += __shfl_xor_sync(0xffffffffu, s, o);
        if (lane == 0) sc[j] = s;
    }
    __syncthreads();
    if (warp == 0) {
        float v0 = sc[lane], v1 = sc[lane + 32];
        float m = fmaxf(v0, v1);
#pragma unroll
        for (int o = 16; o; o >>= 1) m = fmaxf(m, __shfl_xor_sync(0xffffffffu, m, o));
        float e0 = expf(v0 - m), e1 = expf(v1 - m);
        float s = e0 + e1;
#pragma unroll
        for (int o = 16; o; o >>= 1) s += __shfl_xor_sync(0xffffffffu, s, o);
        sc[lane] = e0 / s;
        sc[lane + 32] = e1 / s;
    }
    __syncthreads();
    for (int cidx = tid; cidx < HH; cidx += 256) {
        float a = 0.f;
#pragma unroll 8
        for (int j = 0; j < 64; j++) a += sc[j] * xb[(size_t)j * HH + cidx];
        ctx[b * HH + cidx] = __float2bfloat16(a);
    }
}

// ---------------- generator GEMM: out[2016,32000] = A[2016,1024]@Wg^T + bg --
// A rows ordered (t,b); output row remapped to (b*63+t). 128x128 tile, 8 warps.
__global__ void __launch_bounds__(256) k_gemm_gen(const bf16* __restrict__ A,
                                                  const bf16* __restrict__ W,
                                                  const float* __restrict__ bias,
                                                  float* __restrict__ out) {
    __shared__ __align__(16) bf16 As[128 * 40];
    __shared__ __align__(16) bf16 Bs[128 * 40];
    const int tid = threadIdx.x, warp = tid >> 5, lane = tid & 31;
    const int wr = warp >> 2, wc = warp & 3;
    const int mblk = blockIdx.y * 128;
    const int nblk = blockIdx.x * 128;
    const int sub = lane >> 3, ri = lane & 7;

    float acc[4][4][4];
#pragma unroll
    for (int a = 0; a < 4; a++)
#pragma unroll
        for (int b = 0; b < 4; b++)
#pragma unroll
            for (int c = 0; c < 4; c++) acc[a][b][c] = 0.f;

    for (int kb = 0; kb < 1024; kb += 32) {
        __syncthreads();
#pragma unroll
        for (int i = 0; i < 4; i++) {
            int v = tid + i * 256;
            if (v < 512) {
                int m = v >> 2, cv = v & 3;
                *(uint4*)&As[m * 40 + cv * 8] =
                    *(const uint4*)(A + (size_t)(mblk + m) * 1024 + kb + cv * 8);
            } else {
                int u = v - 512;
                int n = u >> 2, cv = u & 3;
                *(uint4*)&Bs[n * 40 + cv * 8] =
                    *(const uint4*)(W + (size_t)(nblk + n) * 1024 + kb + cv * 8);
            }
        }
        __syncthreads();
#pragma unroll
        for (int kk = 0; kk < 32; kk += 16) {
            uint32_t a[4][4], b[4][2];
#pragma unroll
            for (int mt = 0; mt < 4; mt++) {
                int row = wr * 64 + mt * 16 + (sub & 1) * 8 + ri;
                int col = kk + (sub >> 1) * 8;
                ldsm4(smem_u32(&As[row * 40 + col]), a[mt][0], a[mt][1], a[mt][2], a[mt][3]);
            }
#pragma unroll
            for (int ntp = 0; ntp < 2; ntp++) {
                int row = wc * 32 + ntp * 16 + (sub >> 1) * 8 + ri;
                int col = kk + (sub & 1) * 8;
                ldsm4(smem_u32(&Bs[row * 40 + col]),
                      b[ntp * 2][0], b[ntp * 2][1], b[ntp * 2 + 1][0], b[ntp * 2 + 1][1]);
            }
#pragma unroll
            for (int mt = 0; mt < 4; mt++)
#pragma unroll
                for (int nt = 0; nt < 4; nt++)
                    mma16816(acc[mt][nt], a[mt][0], a[mt][1], a[mt][2], a[mt][3],
                             b[nt][0], b[nt][1]);
        }
    }

    const int r0 = lane >> 2, c0 = (lane & 3) * 2;
#pragma unroll
    for (int mt = 0; mt < 4; mt++) {
#pragma unroll
        for (int nt = 0; nt < 4; nt++) {
            int n = nblk + wc * 32 + nt * 8 + c0;
            float bv0 = bias[n], bv1 = bias[n + 1];
#pragma unroll
            for (int half = 0; half < 2; half++) {
                int m = mblk + wr * 64 + mt * 16 + r0 + half * 8;
                if (m < NSTEP * NB) {
                    int t = m >> 5, bb = m & 31;
                    size_t orow = (size_t)(bb * NSTEP + t) * VV;
                    out[orow + n]     = acc[mt][nt][half * 2 + 0] + bv0;
                    out[orow + n + 1] = acc[mt][nt][half * 2 + 1] + bv1;
                }
            }
        }
    }
}

// ---------------- log_softmax in place (one block per row) ------------------
__global__ void __launch_bounds__(256) k_lsm(float* __restrict__ out) {
    int row = blockIdx.x;
    float* p = out + (size_t)row * VV;
    __shared__ float red[256];
    int tid = threadIdx.x;
    float m = -1e30f;
    for (int i = tid; i < VV; i += 256) m = fmaxf(m, p[i]);
    red[tid] = m;
    __syncthreads();
    for (int s = 128; s; s >>= 1) {
        if (tid < s) red[tid] = fmaxf(red[tid], red[tid + s]);
        __syncthreads();
    }
    m = red[0];
    __syncthreads();
    float sum = 0.f;
    for (int i = tid; i < VV; i += 256) sum += expf(p[i] - m);
    red[tid] = sum;
    __syncthreads();
    for (int s = 128; s; s >>= 1) {
        if (tid < s) red[tid] += red[tid + s];
        __syncthreads();
    }
    float lse = m + logf(red[0]);
    for (int i = tid; i < VV; i += 256) p[i] -= lse;
}

// ---------------- host orchestration ---------------------------------------
static void* sym(const void* s) {
    void* p = nullptr;
    cudaGetSymbolAddress(&p, s);
    return p;
}

extern "C" void kernel_launch(void* const* d_in, const int* in_sizes, int n_in,
                              void* d_out, int out_size) {
    const int*   x     = (const int*)d_in[0];
    const float* h0    = (const float*)d_in[1];
    const float* c0    = (const float*)d_in[2];
    const float* x_enc = (const float*)d_in[3];
    const float* emb   = (const float*)d_in[4];
    const float* Wih0  = (const float*)d_in[5];
    const float* Whh0  = (const float*)d_in[6];
    const float* bih0  = (const float*)d_in[7];
    const float* bhh0  = (const float*)d_in[8];
    const float* Wih1  = (const float*)d_in[9];
    const float* Whh1  = (const float*)d_in[10];
    const float* bih1  = (const float*)d_in[11];
    const float* bhh1  = (const float*)d_in[12];
    const float* Wa    = (const float*)d_in[13];
    const float* ba    = (const float*)d_in[14];
    const float* Wl    = (const float*)d_in[15];
    const float* bl    = (const float*)d_in[16];
    const float* Wg    = (const float*)d_in[17];
    const float* bg    = (const float*)d_in[18];
    float* out = (float*)d_out;

    bf16* pW0   = (bf16*)sym(g_W0);
    bf16* pW1   = (bf16*)sym(g_W1);
    bf16* pWa   = (bf16*)sym(g_Wa);
    bf16* pWl   = (bf16*)sym(g_Wl);
    bf16* pWg   = (bf16*)sym(g_Wg);
    bf16* pEs   = (bf16*)sym(g_eseq);
    bf16* pOuts = (bf16*)sym(g_outs);
    float* pb0  = (float*)sym(g_b0);
    float* pb1  = (float*)sym(g_b1);
    float* pG   = (float*)sym(g_gates);
    bf16* ph0   = (bf16*)sym(g_h0);
    bf16* ph1   = (bf16*)sym(g_h1);
    float* pc0  = (float*)sym(g_c0);
    float* pc1  = (float*)sym(g_c1);
    float* pq   = (float*)sym(g_q);
    bf16* pctx  = (bf16*)sym(g_ctx);

    // --- conversions (once per launch) ---
    {
        int n;
        n = 4096 * 2560; k_cvt_pair<<<(n + 255) / 256, 256>>>(pW0, Wih0, 1536, Whh0, 1024, 4096);
        n = 4096 * 2048; k_cvt_pair<<<(n + 255) / 256, 256>>>(pW1, Wih1, 1024, Whh1, 1024, 4096);
        n = 1024 * 1024; k_cvt<<<(n + 255) / 256, 256>>>(pWa, Wa, n);
        n = 1024 * 2048; k_cvt<<<(n + 255) / 256, 256>>>(pWl, Wl, n);
        n = 32000 * 1024; k_cvt<<<(n + 255) / 256, 256>>>(pWg, Wg, n);
        k_addb<<<16, 256>>>(pb0, bih0, bhh0, 4096);
        k_addb<<<16, 256>>>(pb1, bih1, bhh1, 4096);
        n = NSTEP * NB * EE; k_embed<<<(n + 255) / 256, 256>>>(pEs, x, emb);
        k_init<<<(NB * HH + 255) / 256, 256>>>(h0, c0);
    }

    // --- recurrence ---
    for (int t = 0; t < NSTEP; t++) {
        const bf16* prev = pOuts + (size_t)t * NB * HH;   // slot t (t=0 -> zeros)
        bf16* outt = pOuts + (size_t)(t + 1) * NB * HH;

        // layer 0 gates: A = [e_t | prev_out | h0], K = 2560
        k_gemm_step<<<32, 128>>>(pEs + (size_t)t * NB * EE, EE,
                                 prev, HH, ph0, HH,
                                 512, 1536, 2560,
                                 pW0, pb0, 4096, pG, nullptr, 0);
        k_cell<<<128, 256>>>(pG, pc0, ph0);

        // layer 1 gates: A = [h0_new | h1_prev], K = 2048
        k_gemm_step<<<32, 128>>>(ph0, HH, ph1, HH, ph1, HH,
                                 1024, 2048, 2048,
                                 pW1, pb1, 4096, pG, nullptr, 0);
        k_cell<<<128, 256>>>(pG, pc1, ph1);

        // q = z @ Wa^T + ba
        k_gemm_step<<<8, 128>>>(ph1, HH, ph1, HH, ph1, HH,
                                1024, 1024, 1024,
                                pWa, ba, 1024, pq, nullptr, 0);
        // attention -> ctx (bf16)
        k_attn<<<32, 256>>>(pq, x_enc, pctx);

        // out = tanh([z|ctx] @ Wl^T + bl), store bf16 into outs slot t+1
        k_gemm_step<<<8, 128>>>(ph1, HH, pctx, HH, pctx, HH,
                                1024, 2048, 2048,
                                pWl, bl, 1024, nullptr, outt, 1);
    }

    // --- generator + log_softmax ---
    dim3 gg(VV / 128, 16);
    k_gemm_gen<<<gg, 256>>>(pOuts + NB * HH, pWg, bg, out);
    k_lsm<<<NSTEP * NB, 256>>>(out);
    (void)in_sizes; (void)n_in; (void)out_size;
}

// round 3
// speedup vs baseline: 3.0583x; 3.0583x over previous
#include <cuda_runtime.h>
#include <cuda_bf16.h>
#include <cstdint>

typedef __nv_bfloat16 bf16;

#define NB 32
#define TT 64
#define NSTEP 63
#define HH 1024
#define VV 32000

// ---------------- static scratch ------------------------------------------
__device__ __align__(16) bf16 g_W0r[4096 * 2048];   // [Wih0[:,512:] | Whh0]
__device__ __align__(16) bf16 g_W1 [4096 * 2048];   // [Wih1 | Whh1]
__device__ __align__(16) bf16 g_W0e[4096 * 512];    // Wih0[:, :512]
__device__ __align__(16) bf16 g_WaT[1024 * 1024];   // Wa^T
__device__ __align__(16) bf16 g_Wlz[1024 * 1024];   // Wl[:, :1024]
__device__ __align__(16) bf16 g_Wlc[1024 * 1024];   // Wl[:, 1024:]
__device__ __align__(16) bf16 g_Wg [32000 * 1024];
__device__ __align__(16) bf16 g_eseq[2048 * 512];   // rows t*32+b, pad rows zero
__device__ __align__(16) float g_eg [2048 * 4096];  // e@W0e^T + b0
__device__ __align__(16) bf16 g_xe[2048 * 1024];    // x_enc bf16
__device__ __align__(16) bf16 g_xa[2048 * 1024];    // x_enc @ Wa
__device__ __align__(16) bf16 g_xc[2048 * 1024];    // x_enc @ Wlc^T
__device__ __align__(16) bf16 g_outs[2048 * 1024];  // slot t rows t*32+b; slot0 zeros
__device__ __align__(16) float g_part[16 * 32 * 4096];
__device__ float g_b0[4096];
__device__ float g_b1[4096];
__device__ __align__(16) bf16 g_h0[NB * HH];
__device__ float g_c0[NB * HH];
__device__ __align__(16) bf16 g_h1[NB * HH];
__device__ float g_c1[NB * HH];
__device__ float g_ctxl[NB * HH];
__device__ float g_badot[2048];

// ---------------- helpers ---------------------------------------------------
__device__ __forceinline__ uint32_t smem_u32(const void* p) {
    return (uint32_t)__cvta_generic_to_shared(p);
}
__device__ __forceinline__ void ldsm4(uint32_t addr, uint32_t& r0, uint32_t& r1,
                                      uint32_t& r2, uint32_t& r3) {
    asm volatile("ldmatrix.sync.aligned.m8n8.x4.shared.b16 {%0,%1,%2,%3}, [%4];"
                 : "=r"(r0), "=r"(r1), "=r"(r2), "=r"(r3) : "r"(addr));
}
__device__ __forceinline__ void mma16816(float* c, uint32_t a0, uint32_t a1,
                                         uint32_t a2, uint32_t a3,
                                         uint32_t b0, uint32_t b1) {
    asm volatile(
        "mma.sync.aligned.m16n8k16.row.col.f32.bf16.bf16.f32 "
        "{%0,%1,%2,%3},{%4,%5,%6,%7},{%8,%9},{%0,%1,%2,%3};"
        : "+f"(c[0]), "+f"(c[1]), "+f"(c[2]), "+f"(c[3])
        : "r"(a0), "r"(a1), "r"(a2), "r"(a3), "r"(b0), "r"(b1));
}
__device__ __forceinline__ float sigmoidf_(float x) { return 1.f / (1.f + expf(-x)); }

// ---------------- conversion kernels ---------------------------------------
__global__ void k_cvt(bf16* dst, const float* src, int n) {
    int i = blockIdx.x * blockDim.x + threadIdx.x;
    if (i < n) dst[i] = __float2bfloat16(src[i]);
}
// dst[r, 0:wA] = A[r*strideA + c], dst[r, wA:wA+wB] = B[r*wB + c-wA]
__global__ void k_cvt_pair_str(bf16* dst, const float* A, int strideA, int wA,
                               const float* B, int wB, int rows) {
    int w = wA + wB;
    int i = blockIdx.x * blockDim.x + threadIdx.x;
    if (i < rows * w) {
        int r = i / w, c = i % w;
        float v = (c < wA) ? A[(size_t)r * strideA + c] : B[(size_t)r * wB + (c - wA)];
        dst[i] = __float2bfloat16(v);
    }
}
__global__ void k_cvt_slice(bf16* dst, const float* src, int strideS, int off,
                            int w, int rows) {
    int i = blockIdx.x * blockDim.x + threadIdx.x;
    if (i < rows * w) {
        int r = i / w, c = i % w;
        dst[i] = __float2bfloat16(src[(size_t)r * strideS + off + c]);
    }
}
__global__ void k_cvt_T(bf16* dst, const float* src) {   // 1024x1024
    int i = blockIdx.x * blockDim.x + threadIdx.x;
    if (i < 1024 * 1024) {
        int n = i >> 10, h = i & 1023;
        dst[i] = __float2bfloat16(src[h * 1024 + n]);
    }
}
__global__ void k_addb(float* dst, const float* a, const float* b, int n) {
    int i = blockIdx.x * blockDim.x + threadIdx.x;
    if (i < n) dst[i] = a[i] + b[i];
}
__global__ void k_embed(bf16* eseq, const int* x, const float* emb) {
    int i = blockIdx.x * blockDim.x + threadIdx.x;
    if (i < NSTEP * NB * 512) {
        int c = i & 511;
        int m = i >> 9;
        int b = m & 31, t = m >> 5;
        int tok = x[b * TT + t];
        eseq[i] = __float2bfloat16(emb[(size_t)tok * 512 + c]);
    }
}
__global__ void k_init(const float* h0in, const float* c0in) {
    int i = blockIdx.x * blockDim.x + threadIdx.x;
    if (i < NB * HH) {
        g_h0[i] = __float2bfloat16(h0in[i]);
        g_h1[i] = __float2bfloat16(h0in[NB * HH + i]);
        g_c0[i] = c0in[i];
        g_c1[i] = c0in[NB * HH + i];
    }
}
__global__ void k_badot(const float* ba, const float* x_enc, float* badot) {
    int warp = threadIdx.x >> 5, lane = threadIdx.x & 31;
    int row = blockIdx.x * 8 + warp;
    const float* xr = x_enc + (size_t)row * 1024;
    float s = 0.f;
    for (int h = lane; h < 1024; h += 32) s += ba[h] * xr[h];
#pragma unroll
    for (int o = 16; o; o >>= 1) s += __shfl_xor_sync(0xffffffffu, s, o);
    if (lane == 0) badot[row] = s;
}

// ---------------- step GEMM with split-K ------------------------------------
// part[(ks*32+m)*N + n] = A[m, kb0:kb0+128] @ W[n, kb0:kb0+128]^T
// A = [A0 | A1], each 1024 cols, row stride 1024 bf16.
__global__ void __launch_bounds__(128) k_step_gemm(
    const bf16* __restrict__ A0, const bf16* __restrict__ A1,
    const bf16* __restrict__ W, int Kw,
    float* __restrict__ part, int N)
{
    __shared__ __align__(16) bf16 Ws[128 * 136];
    __shared__ __align__(16) bf16 As[32 * 136];
    const int tid = threadIdx.x, warp = tid >> 5, lane = tid & 31;
    const int nblk = blockIdx.x * 128;
    const int ks = blockIdx.y;
    const int kb0 = ks * 128;
    const bf16* A = (kb0 < 1024) ? (A0 + kb0) : (A1 + (kb0 - 1024));
    const bf16* Wp = W + (size_t)nblk * Kw + kb0;

#pragma unroll
    for (int i = 0; i < 20; i++) {
        int v = tid + i * 128;
        if (v < 2048) {
            int r = v >> 4, c = v & 15;
            *(uint4*)&Ws[r * 136 + c * 8] = *(const uint4*)(Wp + (size_t)r * Kw + c * 8);
        } else {
            int u = v - 2048;
            int r = u >> 4, c = u & 15;
            *(uint4*)&As[r * 136 + c * 8] = *(const uint4*)(A + (size_t)r * 1024 + c * 8);
        }
    }
    __syncthreads();

    const int sub = lane >> 3, ri = lane & 7;
    float acc[2][4][4];
#pragma unroll
    for (int a = 0; a < 2; a++)
#pragma unroll
        for (int b = 0; b < 4; b++)
#pragma unroll
            for (int c = 0; c < 4; c++) acc[a][b][c] = 0.f;

#pragma unroll
    for (int kk = 0; kk < 128; kk += 16) {
        uint32_t a[2][4], b[4][2];
#pragma unroll
        for (int mt = 0; mt < 2; mt++) {
            int row = mt * 16 + (sub & 1) * 8 + ri;
            int col = kk + (sub >> 1) * 8;
            ldsm4(smem_u32(&As[row * 136 + col]), a[mt][0], a[mt][1], a[mt][2], a[mt][3]);
        }
#pragma unroll
        for (int ntp = 0; ntp < 2; ntp++) {
            int row = warp * 32 + ntp * 16 + (sub >> 1) * 8 + ri;
            int col = kk + (sub & 1) * 8;
            ldsm4(smem_u32(&Ws[row * 136 + col]),
                  b[ntp * 2][0], b[ntp * 2][1], b[ntp * 2 + 1][0], b[ntp * 2 + 1][1]);
        }
#pragma unroll
        for (int mt = 0; mt < 2; mt++)
#pragma unroll
            for (int nt = 0; nt < 4; nt++)
                mma16816(acc[mt][nt], a[mt][0], a[mt][1], a[mt][2], a[mt][3],
                         b[nt][0], b[nt][1]);
    }

    const int r0 = lane >> 2, c0 = (lane & 3) * 2;
#pragma unroll
    for (int mt = 0; mt < 2; mt++)
#pragma unroll
        for (int nt = 0; nt < 4; nt++) {
            int m = mt * 16 + r0;
            int n = nblk + warp * 32 + nt * 8 + c0;
            part[(size_t)(ks * 32 + m) * N + n]           = acc[mt][nt][0];
            part[(size_t)(ks * 32 + m) * N + n + 1]       = acc[mt][nt][1];
            part[(size_t)(ks * 32 + m + 8) * N + n]       = acc[mt][nt][2];
            part[(size_t)(ks * 32 + m + 8) * N + n + 1]   = acc[mt][nt][3];
        }
}

// ---------------- cell0: sum 16 partials + eg, LSTM math --------------------
__global__ void k_cell0(const float* __restrict__ eg_t) {
    int i = blockIdx.x * blockDim.x + threadIdx.x;   // 32768
    int b = i >> 10, u = i & 1023;
    const float* base = eg_t + (size_t)b * 4096;
    float ig = base[u], fg = base[1024 + u], gg = base[2048 + u], og = base[3072 + u];
#pragma unroll
    for (int ks = 0; ks < 16; ks++) {
        const float* p = g_part + (size_t)(ks * 32 + b) * 4096;
        ig += p[u]; fg += p[1024 + u]; gg += p[2048 + u]; og += p[3072 + u];
    }
    float cn = sigmoidf_(fg) * g_c0[i] + sigmoidf_(ig) * tanhf(gg);
    g_c0[i] = cn;
    g_h0[i] = __float2bfloat16(sigmoidf_(og) * tanhf(cn));
}

// ---------------- attention + cell1 fused ------------------------------------
__global__ void __launch_bounds__(256) k_attn_cell1() {
    int b = blockIdx.x, tid = threadIdx.x;
    __shared__ float h1s[1024];
    __shared__ float sc[64];

    for (int u = tid; u < 1024; u += 256) {
        float ig = g_b1[u], fg = g_b1[1024 + u], gg = g_b1[2048 + u], og = g_b1[3072 + u];
#pragma unroll
        for (int ks = 0; ks < 16; ks++) {
            const float* p = g_part + (size_t)(ks * 32 + b) * 4096;
            ig += p[u]; fg += p[1024 + u]; gg += p[2048 + u]; og += p[3072 + u];
        }
        float cn = sigmoidf_(fg) * g_c1[b * 1024 + u] + sigmoidf_(ig) * tanhf(gg);
        g_c1[b * 1024 + u] = cn;
        float hv = sigmoidf_(og) * tanhf(cn);
        h1s[u] = hv;
        g_h1[b * 1024 + u] = __float2bfloat16(hv);
    }
    __syncthreads();

    int warp = tid >> 5, lane = tid & 31;
#pragma unroll
    for (int jj = 0; jj < 8; jj++) {
        int j = warp * 8 + jj;
        const bf16* xr = g_xa + (size_t)(b * 64 + j) * 1024;
        float s = 0.f;
        for (int k = lane; k < 1024; k += 32) s += h1s[k] * __bfloat162float(xr[k]);
#pragma unroll
        for (int o = 16; o; o >>= 1) s += __shfl_xor_sync(0xffffffffu, s, o);
        if (lane == 0) sc[j] = s + g_badot[b * 64 + j];
    }
    __syncthreads();
    if (warp == 0) {
        float v0 = sc[lane], v1 = sc[lane + 32];
        float m = fmaxf(v0, v1);
#pragma unroll
        for (int o = 16; o; o >>= 1) m = fmaxf(m, __shfl_xor_sync(0xffffffffu, m, o));
        float e0 = expf(v0 - m), e1 = expf(v1 - m);
        float s = e0 + e1;
#pragma unroll
        for (int o = 16; o; o >>= 1) s += __shfl_xor_sync(0xffffffffu, s, o);
        sc[lane] = e0 / s;
        sc[lane + 32] = e1 / s;
    }
    __syncthreads();
    for (int n = tid; n < 1024; n += 256) {
        float a = 0.f;
#pragma unroll 8
        for (int j = 0; j < 64; j++)
            a += sc[j] * __bfloat162float(g_xc[(size_t)(b * 64 + j) * 1024 + n]);
        g_ctxl[b * 1024 + n] = a;
    }
}

// ---------------- out epilogue: sum 8 wl-partials + ctx + bias, tanh ---------
__global__ void k_out(const float* __restrict__ bl, bf16* __restrict__ outt) {
    int i = blockIdx.x * blockDim.x + threadIdx.x;   // 32768
    int b = i >> 10, u = i & 1023;
    float v = bl[u] + g_ctxl[i];
#pragma unroll
    for (int ks = 0; ks < 8; ks++) v += g_part[(size_t)(ks * 32 + b) * 1024 + u];
    outt[i] = __float2bfloat16(tanhf(v));
}

// ---------------- generic 128x128 GEMM (precompute) --------------------------
// C[m,n] = sum_k A[m,k] W[n,k]; mode 0: fp32 + bias; mode 1: bf16 no bias
__global__ void __launch_bounds__(256) k_gemm_big(
    const bf16* __restrict__ A, const bf16* __restrict__ W,
    const float* __restrict__ bias, float* __restrict__ Cf, bf16* __restrict__ Cb,
    int N, int K, int mode)
{
    __shared__ __align__(16) bf16 As[128 * 40];
    __shared__ __align__(16) bf16 Bs[128 * 40];
    const int tid = threadIdx.x, warp = tid >> 5, lane = tid & 31;
    const int wr = warp >> 2, wc = warp & 3;
    const int mblk = blockIdx.y * 128;
    const int nblk = blockIdx.x * 128;
    const int sub = lane >> 3, ri = lane & 7;

    float acc[4][4][4];
#pragma unroll
    for (int a = 0; a < 4; a++)
#pragma unroll
        for (int b = 0; b < 4; b++)
#pragma unroll
            for (int c = 0; c < 4; c++) acc[a][b][c] = 0.f;

    for (int kb = 0; kb < K; kb += 32) {
        __syncthreads();
#pragma unroll
        for (int i = 0; i < 4; i++) {
            int v = tid + i * 256;
            if (v < 512) {
                int m = v >> 2, cv = v & 3;
                *(uint4*)&As[m * 40 + cv * 8] =
                    *(const uint4*)(A + (size_t)(mblk + m) * K + kb + cv * 8);
            } else {
                int u = v - 512;
                int n = u >> 2, cv = u & 3;
                *(uint4*)&Bs[n * 40 + cv * 8] =
                    *(const uint4*)(W + (size_t)(nblk + n) * K + kb + cv * 8);
            }
        }
        __syncthreads();
#pragma unroll
        for (int kk = 0; kk < 32; kk += 16) {
            uint32_t a[4][4], b[4][2];
#pragma unroll
            for (int mt = 0; mt < 4; mt++) {
                int row = wr * 64 + mt * 16 + (sub & 1) * 8 + ri;
                int col = kk + (sub >> 1) * 8;
                ldsm4(smem_u32(&As[row * 40 + col]), a[mt][0], a[mt][1], a[mt][2], a[mt][3]);
            }
#pragma unroll
            for (int ntp = 0; ntp < 2; ntp++) {
                int row = wc * 32 + ntp * 16 + (sub >> 1) * 8 + ri;
                int col = kk + (sub & 1) * 8;
                ldsm4(smem_u32(&Bs[row * 40 + col]),
                      b[ntp * 2][0], b[ntp * 2][1], b[ntp * 2 + 1][0], b[ntp * 2 + 1][1]);
            }
#pragma unroll
            for (int mt = 0; mt < 4; mt++)
#pragma unroll
                for (int nt = 0; nt < 4; nt++)
                    mma16816(acc[mt][nt], a[mt][0], a[mt][1], a[mt][2], a[mt][3],
                             b[nt][0], b[nt][1]);
        }
    }

    const int r0 = lane >> 2, c0 = (lane & 3) * 2;
#pragma unroll
    for (int mt = 0; mt < 4; mt++)
#pragma unroll
        for (int nt = 0; nt < 4; nt++) {
            int n = nblk + wc * 32 + nt * 8 + c0;
#pragma unroll
            for (int half = 0; half < 2; half++) {
                int m = mblk + wr * 64 + mt * 16 + r0 + half * 8;
                float v0 = acc[mt][nt][half * 2 + 0];
                float v1 = acc[mt][nt][half * 2 + 1];
                if (mode == 0) {
                    Cf[(size_t)m * N + n]     = v0 + bias[n];
                    Cf[(size_t)m * N + n + 1] = v1 + bias[n + 1];
                } else {
                    Cb[(size_t)m * N + n]     = __float2bfloat16(v0);
                    Cb[(size_t)m * N + n + 1] = __float2bfloat16(v1);
                }
            }
        }
}

// ---------------- generator GEMM 256x128 tiles -------------------------------
__global__ void __launch_bounds__(256) k_gen(const bf16* __restrict__ A,
                                             const bf16* __restrict__ W,
                                             const float* __restrict__ bias,
                                             float* __restrict__ out) {
    __shared__ __align__(16) bf16 As[256 * 40];
    __shared__ __align__(16) bf16 Ws[128 * 40];
    const int tid = threadIdx.x, warp = tid >> 5, lane = tid & 31;
    const int wr = warp >> 1, wc = warp & 1;
    const int mblk = blockIdx.y * 256;
    const int nblk = blockIdx.x * 128;
    const int sub = lane >> 3, ri = lane & 7;

    float acc[4][8][4];
#pragma unroll
    for (int a = 0; a < 4; a++)
#pragma unroll
        for (int b = 0; b < 8; b++)
#pragma unroll
            for (int c = 0; c < 4; c++) acc[a][b][c] = 0.f;

    for (int kb = 0; kb < 1024; kb += 32) {
        __syncthreads();
#pragma unroll
        for (int i = 0; i < 6; i++) {
            int v = tid + i * 256;
            if (v < 1024) {
                int m = v >> 2, cv = v & 3;
                *(uint4*)&As[m * 40 + cv * 8] =
                    *(const uint4*)(A + (size_t)(mblk + m) * 1024 + kb + cv * 8);
            } else {
                int u = v - 1024;
                int n = u >> 2, cv = u & 3;
                *(uint4*)&Ws[n * 40 + cv * 8] =
                    *(const uint4*)(W + (size_t)(nblk + n) * 1024 + kb + cv * 8);
            }
        }
        __syncthreads();
#pragma unroll
        for (int kk = 0; kk < 32; kk += 16) {
            uint32_t a[4][4], b[8][2];
#pragma unroll
            for (int mt = 0; mt < 4; mt++) {
                int row = wr * 64 + mt * 16 + (sub & 1) * 8 + ri;
                int col = kk + (sub >> 1) * 8;
                ldsm4(smem_u32(&As[row * 40 + col]), a[mt][0], a[mt][1], a[mt][2], a[mt][3]);
            }
#pragma unroll
            for (int ntp = 0; ntp < 4; ntp++) {
                int row = wc * 64 + ntp * 16 + (sub >> 1) * 8 + ri;
                int col = kk + (sub & 1) * 8;
                ldsm4(smem_u32(&Ws[row * 40 + col]),
                      b[ntp * 2][0], b[ntp * 2][1], b[ntp * 2 + 1][0], b[ntp * 2 + 1][1]);
            }
#pragma unroll
            for (int mt = 0; mt < 4; mt++)
#pragma unroll
                for (int nt = 0; nt < 8; nt++)
                    mma16816(acc[mt][nt], a[mt][0], a[mt][1], a[mt][2], a[mt][3],
                             b[nt][0], b[nt][1]);
        }
    }

    const int r0 = lane >> 2, c0 = (lane & 3) * 2;
#pragma unroll
    for (int mt = 0; mt < 4; mt++)
#pragma unroll
        for (int nt = 0; nt < 8; nt++) {
            int n = nblk + wc * 64 + nt * 8 + c0;
            float bv0 = bias[n], bv1 = bias[n + 1];
#pragma unroll
            for (int half = 0; half < 2; half++) {
                int m = mblk + wr * 64 + mt * 16 + r0 + half * 8;
                if (m < NSTEP * NB) {
                    int t = m >> 5, bb = m & 31;
                    size_t orow = (size_t)(bb * NSTEP + t) * VV;
                    out[orow + n]     = acc[mt][nt][half * 2 + 0] + bv0;
                    out[orow + n + 1] = acc[mt][nt][half * 2 + 1] + bv1;
                }
            }
        }
}

// ---------------- log_softmax (vectorized) -----------------------------------
__global__ void __launch_bounds__(256) k_lsm(float* __restrict__ out) {
    int row = blockIdx.x;
    float4* p = (float4*)(out + (size_t)row * VV);   // 8000 float4
    __shared__ float red[256];
    int tid = threadIdx.x;
    float m = -1e30f;
    for (int i = tid; i < 8000; i += 256) {
        float4 v = p[i];
        m = fmaxf(m, fmaxf(fmaxf(v.x, v.y), fmaxf(v.z, v.w)));
    }
    red[tid] = m;
    __syncthreads();
    for (int s = 128; s; s >>= 1) {
        if (tid < s) red[tid] = fmaxf(red[tid], red[tid + s]);
        __syncthreads();
    }
    m = red[0];
    __syncthreads();
    float sum = 0.f;
    for (int i = tid; i < 8000; i += 256) {
        float4 v = p[i];
        sum += expf(v.x - m) + expf(v.y - m) + expf(v.z - m) + expf(v.w - m);
    }
    red[tid] = sum;
    __syncthreads();
    for (int s = 128; s; s >>= 1) {
        if (tid < s) red[tid] += red[tid + s];
        __syncthreads();
    }
    float lse = m + logf(red[0]);
    for (int i = tid; i < 8000; i += 256) {
        float4 v = p[i];
        v.x -= lse; v.y -= lse; v.z -= lse; v.w -= lse;
        p[i] = v;
    }
}

// ---------------- host --------------------------------------------------------
static void* sym(const void* s) {
    void* p = nullptr;
    cudaGetSymbolAddress(&p, s);
    return p;
}

extern "C" void kernel_launch(void* const* d_in, const int* in_sizes, int n_in,
                              void* d_out, int out_size) {
    const int*   x     = (const int*)d_in[0];
    const float* h0in  = (const float*)d_in[1];
    const float* c0in  = (const float*)d_in[2];
    const float* x_enc = (const float*)d_in[3];
    const float* emb   = (const float*)d_in[4];
    const float* Wih0  = (const float*)d_in[5];
    const float* Whh0  = (const float*)d_in[6];
    const float* bih0  = (const float*)d_in[7];
    const float* bhh0  = (const float*)d_in[8];
    const float* Wih1  = (const float*)d_in[9];
    const float* Whh1  = (const float*)d_in[10];
    const float* bih1  = (const float*)d_in[11];
    const float* bhh1  = (const float*)d_in[12];
    const float* Wa    = (const float*)d_in[13];
    const float* ba    = (const float*)d_in[14];
    const float* Wl    = (const float*)d_in[15];
    const float* bl    = (const float*)d_in[16];
    const float* Wg    = (const float*)d_in[17];
    const float* bg    = (const float*)d_in[18];
    float* out = (float*)d_out;

    bf16*  pW0r = (bf16*)sym(g_W0r);
    bf16*  pW1  = (bf16*)sym(g_W1);
    bf16*  pW0e = (bf16*)sym(g_W0e);
    bf16*  pWaT = (bf16*)sym(g_WaT);
    bf16*  pWlz = (bf16*)sym(g_Wlz);
    bf16*  pWlc = (bf16*)sym(g_Wlc);
    bf16*  pWg  = (bf16*)sym(g_Wg);
    bf16*  pEs  = (bf16*)sym(g_eseq);
    float* pEg  = (float*)sym(g_eg);
    bf16*  pXe  = (bf16*)sym(g_xe);
    bf16*  pXa  = (bf16*)sym(g_xa);
    bf16*  pXc  = (bf16*)sym(g_xc);
    bf16*  pOuts= (bf16*)sym(g_outs);
    float* pPart= (float*)sym(g_part);
    float* pB0  = (float*)sym(g_b0);
    float* pB1  = (float*)sym(g_b1);
    bf16*  pH0  = (bf16*)sym(g_h0);
    bf16*  pH1  = (bf16*)sym(g_h1);
    float* pBad = (float*)sym(g_badot);

    // ---- precompute (loop-invariant) ----
    {
        int n;
        n = 4096 * 2048;
        k_cvt_pair_str<<<(n + 255) / 256, 256>>>(pW0r, Wih0 + 512, 1536, 1024, Whh0, 1024, 4096);
        k_cvt_pair_str<<<(n + 255) / 256, 256>>>(pW1, Wih1, 1024, 1024, Whh1, 1024, 4096);
        n = 4096 * 512;
        k_cvt_slice<<<(n + 255) / 256, 256>>>(pW0e, Wih0, 1536, 0, 512, 4096);
        n = 1024 * 1024;
        k_cvt_T<<<(n + 255) / 256, 256>>>(pWaT, Wa);
        k_cvt_slice<<<(n + 255) / 256, 256>>>(pWlz, Wl, 2048, 0, 1024, 1024);
        k_cvt_slice<<<(n + 255) / 256, 256>>>(pWlc, Wl, 2048, 1024, 1024, 1024);
        n = 32000 * 1024;
        k_cvt<<<(n + 255) / 256, 256>>>(pWg, Wg, n);
        n = 2048 * 1024;
        k_cvt<<<(n + 255) / 256, 256>>>(pXe, x_enc, n);
        k_addb<<<16, 256>>>(pB0, bih0, bhh0, 4096);
        k_addb<<<16, 256>>>(pB1, bih1, bhh1, 4096);
        n = NSTEP * NB * 512;
        k_embed<<<(n + 255) / 256, 256>>>(pEs, x, emb);
        k_init<<<128, 256>>>(h0in, c0in);
        k_badot<<<256, 256>>>(ba, x_enc, pBad);
        // eg = eseq @ W0e^T + b0   [2048, 4096]
        k_gemm_big<<<dim3(32, 16), 256>>>(pEs, pW0e, pB0, pEg, nullptr, 4096, 512, 0);
        // xa = xe @ WaT^T = x_enc @ Wa  [2048, 1024]
        k_gemm_big<<<dim3(8, 16), 256>>>(pXe, pWaT, nullptr, nullptr, pXa, 1024, 1024, 1);
        // xc = xe @ Wlc^T  [2048, 1024]
        k_gemm_big<<<dim3(8, 16), 256>>>(pXe, pWlc, nullptr, nullptr, pXc, 1024, 1024, 1);
    }

    // ---- recurrence ----
    for (int t = 0; t < NSTEP; t++) {
        const bf16* prev = pOuts + (size_t)t * NB * HH;        // slot t (zeros at t=0)
        bf16* outt = pOuts + (size_t)(t + 1) * NB * HH;
        const float* eg_t = pEg + (size_t)t * NB * 4096;

        // layer0 gates: [prev | h0] @ W0r^T  -> 16 partials
        k_step_gemm<<<dim3(32, 16), 128>>>(prev, pH0, pW0r, 2048, pPart, 4096);
        k_cell0<<<128, 256>>>(eg_t);

        // layer1 gates: [h0 | h1] @ W1^T
        k_step_gemm<<<dim3(32, 16), 128>>>(pH0, pH1, pW1, 2048, pPart, 4096);
        // cell1 + attention (scores via xa, ctx-proj via xc)
        k_attn_cell1<<<32, 256>>>();

        // wl_z: h1 @ Wlz^T  (K=1024 -> 8 splits)
        k_step_gemm<<<dim3(8, 8), 128>>>(pH1, pH1, pWlz, 1024, pPart, 1024);
        k_out<<<128, 256>>>(bl, outt);
    }

    // ---- generator + log_softmax ----
    k_gen<<<dim3(250, 8), 256>>>(pOuts + NB * HH, pWg, bg, out);
    k_lsm<<<NSTEP * NB, 256>>>(out);

    (void)in_sizes; (void)n_in; (void)out_size;
}

// round 4
// speedup vs baseline: 3.5667x; 1.1662x over previous
#include <cuda_runtime.h>
#include <cuda_bf16.h>
#include <cstdint>

typedef __nv_bfloat16 bf16;

#define NB 32
#define TT 64
#define NSTEP 63
#define HH 1024
#define VV 32000
#define GRID_P 148           // persistent grid (one CTA per SM)

// ---------------- static scratch --------------------------------------------
__device__ __align__(16) bf16 g_W0i[4096 * 2560];   // [Wih0 | Whh0], rows interleaved 4u+gate
__device__ __align__(16) bf16 g_W1i[4096 * 2048];   // [Wih1 | Whh1], interleaved
__device__ __align__(16) bf16 g_WaT[1024 * 1024];   // Wa^T
__device__ __align__(16) bf16 g_Wlz[1024 * 1024];   // Wl[:, :1024]
__device__ __align__(16) bf16 g_Wlc[1024 * 1024];   // Wl[:, 1024:]
__device__ __align__(16) bf16 g_Wg [32000 * 1024];
__device__ __align__(16) bf16 g_eseq[2048 * 512];   // rows t*32+b (pad rows stay 0)
__device__ __align__(16) bf16 g_xe[2048 * 1024];
__device__ __align__(16) bf16 g_xa[2048 * 1024];
__device__ __align__(16) bf16 g_xc[2048 * 1024];
__device__ __align__(16) bf16 g_outs[2080 * 1024];  // slot t rows t*32+b; slot0 zeros
__device__ float g_b0i[4096];
__device__ float g_b1i[4096];
__device__ __align__(16) bf16 g_h0buf[2 * NB * HH];
__device__ __align__(16) bf16 g_h1buf[2 * NB * HH];
__device__ float g_c0[NB * HH];
__device__ float g_c1[NB * HH];
__device__ float g_ctxl[NB * HH];
__device__ float g_wl[NB * HH];
__device__ float g_badot[2048];
__device__ unsigned long long g_bar_cnt;   // monotonic, never reset
__device__ unsigned long long g_bar_gen;

// ---------------- helpers ----------------------------------------------------
__device__ __forceinline__ uint32_t smem_u32(const void* p) {
    return (uint32_t)__cvta_generic_to_shared(p);
}
__device__ __forceinline__ void ldsm4(uint32_t addr, uint32_t& r0, uint32_t& r1,
                                      uint32_t& r2, uint32_t& r3) {
    asm volatile("ldmatrix.sync.aligned.m8n8.x4.shared.b16 {%0,%1,%2,%3}, [%4];"
                 : "=r"(r0), "=r"(r1), "=r"(r2), "=r"(r3) : "r"(addr));
}
__device__ __forceinline__ void mma16816(float* c, uint32_t a0, uint32_t a1,
                                         uint32_t a2, uint32_t a3,
                                         uint32_t b0, uint32_t b1) {
    asm volatile(
        "mma.sync.aligned.m16n8k16.row.col.f32.bf16.bf16.f32 "
        "{%0,%1,%2,%3},{%4,%5,%6,%7},{%8,%9},{%0,%1,%2,%3};"
        : "+f"(c[0]), "+f"(c[1]), "+f"(c[2]), "+f"(c[3])
        : "r"(a0), "r"(a1), "r"(a2), "r"(a3), "r"(b0), "r"(b1));
}
__device__ __forceinline__ float sigmoidf_(float x) { return 1.f / (1.f + expf(-x)); }

// grid-wide barrier: monotonic ticket counter + generation, acquire-release
__device__ __forceinline__ void gbar() {
    __syncthreads();
    if (threadIdx.x == 0) {
        __threadfence();
        unsigned long long arrive = atomicAdd(&g_bar_cnt, 1ULL);
        unsigned long long target = arrive / GRID_P + 1ULL;
        if ((arrive % GRID_P) == GRID_P - 1) {
            atomicAdd(&g_bar_gen, 1ULL);
        } else {
            unsigned long long g;
            do {
                __nanosleep(32);
                asm volatile("ld.acquire.gpu.global.u64 %0, [%1];"
                             : "=l"(g) : "l"(&g_bar_gen));
            } while (g < target);
        }
        __threadfence();
    }
    __syncthreads();
}

// ---------------- conversion / precompute kernels ----------------------------
__global__ void k_cvt(bf16* dst, const float* src, int n) {
    int i = blockIdx.x * blockDim.x + threadIdx.x;
    if (i < n) dst[i] = __float2bfloat16(src[i]);
}
__global__ void k_cvt_w0_i(bf16* dst, const float* Wih0, const float* Whh0) {
    int i = blockIdx.x * blockDim.x + threadIdx.x;    // 4096*2560
    if (i < 4096 * 2560) {
        int rn = i / 2560, c = i % 2560;
        int u = rn >> 2, g = rn & 3;
        int srow = g * 1024 + u;
        float v = (c < 1536) ? Wih0[(size_t)srow * 1536 + c]
                             : Whh0[(size_t)srow * 1024 + (c - 1536)];
        dst[i] = __float2bfloat16(v);
    }
}
__global__ void k_cvt_w1_i(bf16* dst, const float* Wih1, const float* Whh1) {
    int i = blockIdx.x * blockDim.x + threadIdx.x;    // 4096*2048
    if (i < 4096 * 2048) {
        int rn = i >> 11, c = i & 2047;
        int u = rn >> 2, g = rn & 3;
        int srow = g * 1024 + u;
        float v = (c < 1024) ? Wih1[(size_t)srow * 1024 + c]
                             : Whh1[(size_t)srow * 1024 + (c - 1024)];
        dst[i] = __float2bfloat16(v);
    }
}
__global__ void k_cvt_slice(bf16* dst, const float* src, int strideS, int off,
                            int w, int rows) {
    int i = blockIdx.x * blockDim.x + threadIdx.x;
    if (i < rows * w) {
        int r = i / w, c = i % w;
        dst[i] = __float2bfloat16(src[(size_t)r * strideS + off + c]);
    }
}
__global__ void k_cvt_T(bf16* dst, const float* src) {   // 1024x1024 transpose
    int i = blockIdx.x * blockDim.x + threadIdx.x;
    if (i < 1024 * 1024) {
        int n = i >> 10, h = i & 1023;
        dst[i] = __float2bfloat16(src[h * 1024 + n]);
    }
}
__global__ void k_addb_i(float* dst, const float* a, const float* b) {
    int i = blockIdx.x * blockDim.x + threadIdx.x;
    if (i < 4096) {
        int u = i >> 2, g = i & 3;
        dst[i] = a[g * 1024 + u] + b[g * 1024 + u];
    }
}
__global__ void k_embed(bf16* eseq, const int* x, const float* emb) {
    int i = blockIdx.x * blockDim.x + threadIdx.x;
    if (i < NSTEP * NB * 512) {
        int c = i & 511;
        int m = i >> 9;
        int b = m & 31, t = m >> 5;
        int tok = x[b * TT + t];
        eseq[i] = __float2bfloat16(emb[(size_t)tok * 512 + c]);
    }
}
__global__ void k_init(const float* h0in, const float* c0in) {
    int i = blockIdx.x * blockDim.x + threadIdx.x;
    if (i < NB * HH) {
        g_h0buf[i] = __float2bfloat16(h0in[i]);
        g_h1buf[i] = __float2bfloat16(h0in[NB * HH + i]);
        g_c0[i] = c0in[i];
        g_c1[i] = c0in[NB * HH + i];
    }
}
__global__ void k_badot(const float* ba, const float* x_enc, float* badot) {
    int warp = threadIdx.x >> 5, lane = threadIdx.x & 31;
    int row = blockIdx.x * 8 + warp;
    const float* xr = x_enc + (size_t)row * 1024;
    float s = 0.f;
    for (int h = lane; h < 1024; h += 32) s += ba[h] * xr[h];
#pragma unroll
    for (int o = 16; o; o >>= 1) s += __shfl_xor_sync(0xffffffffu, s, o);
    if (lane == 0) badot[row] = s;
}

// ---------------- generic 128x128 GEMM (precompute xa, xc) -------------------
__global__ void __launch_bounds__(256) k_gemm_big(
    const bf16* __restrict__ A, const bf16* __restrict__ W,
    bf16* __restrict__ Cb, int N, int K)
{
    __shared__ __align__(16) bf16 As[128 * 40];
    __shared__ __align__(16) bf16 Bs[128 * 40];
    const int tid = threadIdx.x, warp = tid >> 5, lane = tid & 31;
    const int wr = warp >> 2, wc = warp & 3;
    const int mblk = blockIdx.y * 128;
    const int nblk = blockIdx.x * 128;
    const int sub = lane >> 3, ri = lane & 7;

    float acc[4][4][4];
#pragma unroll
    for (int a = 0; a < 4; a++)
#pragma unroll
        for (int b = 0; b < 4; b++)
#pragma unroll
            for (int c = 0; c < 4; c++) acc[a][b][c] = 0.f;

    for (int kb = 0; kb < K; kb += 32) {
        __syncthreads();
#pragma unroll
        for (int i = 0; i < 4; i++) {
            int v = tid + i * 256;
            if (v < 512) {
                int m = v >> 2, cv = v & 3;
                *(uint4*)&As[m * 40 + cv * 8] =
                    *(const uint4*)(A + (size_t)(mblk + m) * K + kb + cv * 8);
            } else {
                int u = v - 512;
                int n = u >> 2, cv = u & 3;
                *(uint4*)&Bs[n * 40 + cv * 8] =
                    *(const uint4*)(W + (size_t)(nblk + n) * K + kb + cv * 8);
            }
        }
        __syncthreads();
#pragma unroll
        for (int kk = 0; kk < 32; kk += 16) {
            uint32_t a[4][4], b[4][2];
#pragma unroll
            for (int mt = 0; mt < 4; mt++) {
                int row = wr * 64 + mt * 16 + (sub & 1) * 8 + ri;
                int col = kk + (sub >> 1) * 8;
                ldsm4(smem_u32(&As[row * 40 + col]), a[mt][0], a[mt][1], a[mt][2], a[mt][3]);
            }
#pragma unroll
            for (int ntp = 0; ntp < 2; ntp++) {
                int row = wc * 32 + ntp * 16 + (sub >> 1) * 8 + ri;
                int col = kk + (sub & 1) * 8;
                ldsm4(smem_u32(&Bs[row * 40 + col]),
                      b[ntp * 2][0], b[ntp * 2][1], b[ntp * 2 + 1][0], b[ntp * 2 + 1][1]);
            }
#pragma unroll
            for (int mt = 0; mt < 4; mt++)
#pragma unroll
                for (int nt = 0; nt < 4; nt++)
                    mma16816(acc[mt][nt], a[mt][0], a[mt][1], a[mt][2], a[mt][3],
                             b[nt][0], b[nt][1]);
        }
    }

    const int r0 = lane >> 2, c0 = (lane & 3) * 2;
#pragma unroll
    for (int mt = 0; mt < 4; mt++)
#pragma unroll
        for (int nt = 0; nt < 4; nt++) {
            int n = nblk + wc * 32 + nt * 8 + c0;
#pragma unroll
            for (int half = 0; half < 2; half++) {
                int m = mblk + wr * 64 + mt * 16 + r0 + half * 8;
                Cb[(size_t)m * N + n]     = __float2bfloat16(acc[mt][nt][half * 2 + 0]);
                Cb[(size_t)m * N + n + 1] = __float2bfloat16(acc[mt][nt][half * 2 + 1]);
            }
        }
}

// ---------------- in-kernel 32xN-tile GEMM (warp split-K, smem reduce) -------
// C[32, 32cols] = A[32, K] @ W[nblk:nblk+32, K]^T. A in up to 3 segments along K
// (boundaries k1,k2, chunk-of-512 aligned). Result: out[4] per thread,
// thread t -> row b = t>>3, cols nblk + (t&7)*4 + 0..3.
__device__ __forceinline__ void gemm32(
    const bf16* __restrict__ A0, int st0,
    const bf16* __restrict__ A1, int st1,
    const bf16* __restrict__ A2, int st2,
    int k1, int k2, int Kw,
    const bf16* __restrict__ W, int nblk,
    bf16* sm, float* red, float out[4])
{
    bf16* As = sm;            // 32 x 520
    bf16* Ws = sm + 32 * 520; // 32 x 520
    const int tid = threadIdx.x, warp = tid >> 5, lane = tid & 31;
    const int sub = lane >> 3, ri = lane & 7;
    float acc[2][4][4];
#pragma unroll
    for (int a = 0; a < 2; a++)
#pragma unroll
        for (int b = 0; b < 4; b++)
#pragma unroll
            for (int c = 0; c < 4; c++) acc[a][b][c] = 0.f;

    const int nchunk = Kw >> 9;
    for (int ch = 0; ch < nchunk; ch++) {
        int k0 = ch << 9;
        const bf16* Asrc; int ast;
        if (k0 < k1)      { Asrc = A0 + k0;        ast = st0; }
        else if (k0 < k2) { Asrc = A1 + (k0 - k1); ast = st1; }
        else              { Asrc = A2 + (k0 - k2); ast = st2; }
        const bf16* Wsrc = W + (size_t)nblk * Kw + k0;
        __syncthreads();
#pragma unroll
        for (int i = 0; i < 8; i++) {
            int v = tid + i * 256;        // 0..2047
            int r = v >> 6, c = v & 63;
            *(uint4*)&As[r * 520 + c * 8] = *(const uint4*)(Asrc + (size_t)r * ast + c * 8);
        }
#pragma unroll
        for (int i = 0; i < 8; i++) {
            int v = tid + i * 256;
            int r = v >> 6, c = v & 63;
            *(uint4*)&Ws[r * 520 + c * 8] = *(const uint4*)(Wsrc + (size_t)r * Kw + c * 8);
        }
        __syncthreads();
#pragma unroll
        for (int kk = 0; kk < 64; kk += 16) {
            int col = (warp << 6) + kk;
            uint32_t a[2][4], b[4][2];
#pragma unroll
            for (int mt = 0; mt < 2; mt++) {
                int row = mt * 16 + (sub & 1) * 8 + ri;
                ldsm4(smem_u32(&As[row * 520 + col + (sub >> 1) * 8]),
                      a[mt][0], a[mt][1], a[mt][2], a[mt][3]);
            }
#pragma unroll
            for (int ntp = 0; ntp < 2; ntp++) {
                int row = ntp * 16 + (sub >> 1) * 8 + ri;
                ldsm4(smem_u32(&Ws[row * 520 + col + (sub & 1) * 8]),
                      b[ntp * 2][0], b[ntp * 2][1], b[ntp * 2 + 1][0], b[ntp * 2 + 1][1]);
            }
#pragma unroll
            for (int mt = 0; mt < 2; mt++)
#pragma unroll
                for (int nt = 0; nt < 4; nt++)
                    mma16816(acc[mt][nt], a[mt][0], a[mt][1], a[mt][2], a[mt][3],
                             b[nt][0], b[nt][1]);
        }
    }
    __syncthreads();
    float* rw = red + warp * (32 * 33);
#pragma unroll
    for (int mt = 0; mt < 2; mt++)
#pragma unroll
        for (int nt = 0; nt < 4; nt++) {
            int m = mt * 16 + (lane >> 2);
            int n0 = nt * 8 + (lane & 3) * 2;
            rw[m * 33 + n0]           = acc[mt][nt][0];
            rw[m * 33 + n0 + 1]       = acc[mt][nt][1];
            rw[(m + 8) * 33 + n0]     = acc[mt][nt][2];
            rw[(m + 8) * 33 + n0 + 1] = acc[mt][nt][3];
        }
    __syncthreads();
    int b = tid >> 3, ul = tid & 7;
#pragma unroll
    for (int g = 0; g < 4; g++) {
        float s = 0.f;
#pragma unroll
        for (int w = 0; w < 8; w++) s += red[w * (32 * 33) + b * 33 + ul * 4 + g];
        out[g] = s;
    }
}

// ---------------- attention (device func, block handles batch b) -------------
__device__ void attn_dev(int b, const bf16* __restrict__ h1, char* smraw) {
    float* h1s = (float*)smraw;
    float* sc = h1s + 1024;
    int tid = threadIdx.x;
    for (int u = tid; u < 1024; u += 256) h1s[u] = __bfloat162float(h1[b * 1024 + u]);
    __syncthreads();
    int warp = tid >> 5, lane = tid & 31;
#pragma unroll
    for (int jj = 0; jj < 8; jj++) {
        int j = warp * 8 + jj;
        const uint4* xr = (const uint4*)(g_xa + (size_t)(b * 64 + j) * 1024);
        float s = 0.f;
        for (int k4 = lane; k4 < 128; k4 += 32) {
            uint4 v = xr[k4];
            const __nv_bfloat162* p2 = (const __nv_bfloat162*)&v;
            int base = k4 * 8;
#pragma unroll
            for (int q = 0; q < 4; q++) {
                float2 f = __bfloat1622float2(p2[q]);
                s += h1s[base + q * 2] * f.x + h1s[base + q * 2 + 1] * f.y;
            }
        }
#pragma unroll
        for (int o = 16; o; o >>= 1) s += __shfl_xor_sync(0xffffffffu, s, o);
        if (lane == 0) sc[j] = s + g_badot[b * 64 + j];
    }
    __syncthreads();
    if (warp == 0) {
        float v0 = sc[lane], v1 = sc[lane + 32];
        float m = fmaxf(v0, v1);
#pragma unroll
        for (int o = 16; o; o >>= 1) m = fmaxf(m, __shfl_xor_sync(0xffffffffu, m, o));
        float e0 = expf(v0 - m), e1 = expf(v1 - m);
        float s = e0 + e1;
#pragma unroll
        for (int o = 16; o; o >>= 1) s += __shfl_xor_sync(0xffffffffu, s, o);
        sc[lane] = e0 / s;
        sc[lane + 32] = e1 / s;
    }
    __syncthreads();
    for (int n = tid; n < 1024; n += 256) {
        float a = 0.f;
#pragma unroll 8
        for (int j = 0; j < 64; j++)
            a += sc[j] * __bfloat162float(g_xc[(size_t)(b * 64 + j) * 1024 + n]);
        g_ctxl[b * 1024 + n] = a;
    }
}

// ---------------- persistent recurrence kernel -------------------------------
#define SMEM_RECUR (2 * 32 * 520 * 2 + 8 * 32 * 33 * 4)   // 66560 + 33792 = 100352

__global__ void __launch_bounds__(256) k_recur(const float* __restrict__ bl) {
    extern __shared__ char smraw[];
    bf16* sm = (bf16*)smraw;
    float* red = (float*)(smraw + 2 * 32 * 520 * 2);
    const int bid = blockIdx.x;
    const int tid = threadIdx.x;

    for (int t = 0; t < NSTEP; t++) {
        const bf16* h0_in  = g_h0buf + (t & 1) * (NB * HH);
        bf16*       h0_out = g_h0buf + ((t + 1) & 1) * (NB * HH);
        const bf16* h1_in  = g_h1buf + (t & 1) * (NB * HH);
        bf16*       h1_out = g_h1buf + ((t + 1) & 1) * (NB * HH);
        const bf16* prev   = g_outs + (size_t)t * (NB * HH);
        const bf16* es_t   = g_eseq + (size_t)t * (NB * 512);

        // P1: layer-0 gates + cell (K = 2560 = [e(512) | prev(1024) | h0(1024)])
        if (bid < 128) {
            float s[4];
            gemm32(es_t, 512, prev, 1024, h0_in, 1024,
                   512, 1536, 2560, g_W0i, bid * 32, sm, red, s);
            int b = tid >> 3, ul = tid & 7;
            int rn = bid * 32 + ul * 4;
            int u = rn >> 2;
            float ig = s[0] + g_b0i[rn];
            float fg = s[1] + g_b0i[rn + 1];
            float gg = s[2] + g_b0i[rn + 2];
            float og = s[3] + g_b0i[rn + 3];
            float cn = sigmoidf_(fg) * g_c0[b * 1024 + u] + sigmoidf_(ig) * tanhf(gg);
            g_c0[b * 1024 + u] = cn;
            h0_out[b * 1024 + u] = __float2bfloat16(sigmoidf_(og) * tanhf(cn));
        }
        gbar();

        // P2: layer-1 gates + cell (K = 2048 = [h0_new | h1_prev])
        if (bid < 128) {
            float s[4];
            gemm32(h0_out, 1024, h1_in, 1024, h1_in, 1024,
                   1024, 2048, 2048, g_W1i, bid * 32, sm, red, s);
            int b = tid >> 3, ul = tid & 7;
            int rn = bid * 32 + ul * 4;
            int u = rn >> 2;
            float ig = s[0] + g_b1i[rn];
            float fg = s[1] + g_b1i[rn + 1];
            float gg = s[2] + g_b1i[rn + 2];
            float og = s[3] + g_b1i[rn + 3];
            float cn = sigmoidf_(fg) * g_c1[b * 1024 + u] + sigmoidf_(ig) * tanhf(gg);
            g_c1[b * 1024 + u] = cn;
            h1_out[b * 1024 + u] = __float2bfloat16(sigmoidf_(og) * tanhf(cn));
        }
        gbar();

        // P3: attention (blocks 0-31) || z @ Wlz^T (blocks 32-63)
        if (bid < 32) {
            attn_dev(bid, h1_out, smraw);
        } else if (bid < 64) {
            float s[4];
            gemm32(h1_out, 1024, h1_out, 1024, h1_out, 1024,
                   1024, 1024, 1024, g_Wlz, (bid - 32) * 32, sm, red, s);
            int b = tid >> 3, ul = tid & 7;
            int n = (bid - 32) * 32 + ul * 4;
#pragma unroll
            for (int g = 0; g < 4; g++) g_wl[b * 1024 + n + g] = s[g];
        }
        gbar();

        // P4: out = tanh(wl + bl + ctx) -> outs slot t+1 (bf16)
        if (bid < 32) {
            bf16* outt = g_outs + (size_t)(t + 1) * (NB * HH) + bid * 1024;
            int n = tid * 4;
#pragma unroll
            for (int j = 0; j < 4; j++) {
                float v = g_wl[bid * 1024 + n + j] + bl[n + j] + g_ctxl[bid * 1024 + n + j];
                outt[n + j] = __float2bfloat16(tanhf(v));
            }
        }
        gbar();
    }
}

// ---------------- generator GEMM 256x128 tiles --------------------------------
__global__ void __launch_bounds__(256) k_gen(const bf16* __restrict__ A,
                                             const bf16* __restrict__ W,
                                             const float* __restrict__ bias,
                                             float* __restrict__ out) {
    __shared__ __align__(16) bf16 As[256 * 40];
    __shared__ __align__(16) bf16 Ws[128 * 40];
    const int tid = threadIdx.x, warp = tid >> 5, lane = tid & 31;
    const int wr = warp >> 1, wc = warp & 1;
    const int mblk = blockIdx.y * 256;
    const int nblk = blockIdx.x * 128;
    const int sub = lane >> 3, ri = lane & 7;

    float acc[4][8][4];
#pragma unroll
    for (int a = 0; a < 4; a++)
#pragma unroll
        for (int b = 0; b < 8; b++)
#pragma unroll
            for (int c = 0; c < 4; c++) acc[a][b][c] = 0.f;

    for (int kb = 0; kb < 1024; kb += 32) {
        __syncthreads();
#pragma unroll
        for (int i = 0; i < 6; i++) {
            int v = tid + i * 256;
            if (v < 1024) {
                int m = v >> 2, cv = v & 3;
                *(uint4*)&As[m * 40 + cv * 8] =
                    *(const uint4*)(A + (size_t)(mblk + m) * 1024 + kb + cv * 8);
            } else {
                int u = v - 1024;
                int n = u >> 2, cv = u & 3;
                *(uint4*)&Ws[n * 40 + cv * 8] =
                    *(const uint4*)(W + (size_t)(nblk + n) * 1024 + kb + cv * 8);
            }
        }
        __syncthreads();
#pragma unroll
        for (int kk = 0; kk < 32; kk += 16) {
            uint32_t a[4][4], b[8][2];
#pragma unroll
            for (int mt = 0; mt < 4; mt++) {
                int row = wr * 64 + mt * 16 + (sub & 1) * 8 + ri;
                int col = kk + (sub >> 1) * 8;
                ldsm4(smem_u32(&As[row * 40 + col]), a[mt][0], a[mt][1], a[mt][2], a[mt][3]);
            }
#pragma unroll
            for (int ntp = 0; ntp < 4; ntp++) {
                int row = wc * 64 + ntp * 16 + (sub >> 1) * 8 + ri;
                int col = kk + (sub & 1) * 8;
                ldsm4(smem_u32(&Ws[row * 40 + col]),
                      b[ntp * 2][0], b[ntp * 2][1], b[ntp * 2 + 1][0], b[ntp * 2 + 1][1]);
            }
#pragma unroll
            for (int mt = 0; mt < 4; mt++)
#pragma unroll
                for (int nt = 0; nt < 8; nt++)
                    mma16816(acc[mt][nt], a[mt][0], a[mt][1], a[mt][2], a[mt][3],
                             b[nt][0], b[nt][1]);
        }
    }

    const int r0 = lane >> 2, c0 = (lane & 3) * 2;
#pragma unroll
    for (int mt = 0; mt < 4; mt++)
#pragma unroll
        for (int nt = 0; nt < 8; nt++) {
            int n = nblk + wc * 64 + nt * 8 + c0;
            float bv0 = bias[n], bv1 = bias[n + 1];
#pragma unroll
            for (int half = 0; half < 2; half++) {
                int m = mblk + wr * 64 + mt * 16 + r0 + half * 8;
                if (m < NSTEP * NB) {
                    int t = m >> 5, bb = m & 31;
                    size_t orow = (size_t)(bb * NSTEP + t) * VV;
                    out[orow + n]     = acc[mt][nt][half * 2 + 0] + bv0;
                    out[orow + n + 1] = acc[mt][nt][half * 2 + 1] + bv1;
                }
            }
        }
}

// ---------------- log_softmax (vectorized, in place) --------------------------
__global__ void __launch_bounds__(256) k_lsm(float* __restrict__ out) {
    int row = blockIdx.x;
    float4* p = (float4*)(out + (size_t)row * VV);
    __shared__ float red[256];
    int tid = threadIdx.x;
    float m = -1e30f;
    for (int i = tid; i < 8000; i += 256) {
        float4 v = p[i];
        m = fmaxf(m, fmaxf(fmaxf(v.x, v.y), fmaxf(v.z, v.w)));
    }
    red[tid] = m;
    __syncthreads();
    for (int s = 128; s; s >>= 1) {
        if (tid < s) red[tid] = fmaxf(red[tid], red[tid + s]);
        __syncthreads();
    }
    m = red[0];
    __syncthreads();
    float sum = 0.f;
    for (int i = tid; i < 8000; i += 256) {
        float4 v = p[i];
        sum += expf(v.x - m) + expf(v.y - m) + expf(v.z - m) + expf(v.w - m);
    }
    red[tid] = sum;
    __syncthreads();
    for (int s = 128; s; s >>= 1) {
        if (tid < s) red[tid] += red[tid + s];
        __syncthreads();
    }
    float lse = m + logf(red[0]);
    for (int i = tid; i < 8000; i += 256) {
        float4 v = p[i];
        v.x -= lse; v.y -= lse; v.z -= lse; v.w -= lse;
        p[i] = v;
    }
}

// ---------------- host ---------------------------------------------------------
static void* sym(const void* s) {
    void* p = nullptr;
    cudaGetSymbolAddress(&p, s);
    return p;
}

extern "C" void kernel_launch(void* const* d_in, const int* in_sizes, int n_in,
                              void* d_out, int out_size) {
    const int*   x     = (const int*)d_in[0];
    const float* h0in  = (const float*)d_in[1];
    const float* c0in  = (const float*)d_in[2];
    const float* x_enc = (const float*)d_in[3];
    const float* emb   = (const float*)d_in[4];
    const float* Wih0  = (const float*)d_in[5];
    const float* Whh0  = (const float*)d_in[6];
    const float* bih0  = (const float*)d_in[7];
    const float* bhh0  = (const float*)d_in[8];
    const float* Wih1  = (const float*)d_in[9];
    const float* Whh1  = (const float*)d_in[10];
    const float* bih1  = (const float*)d_in[11];
    const float* bhh1  = (const float*)d_in[12];
    const float* Wa    = (const float*)d_in[13];
    const float* ba    = (const float*)d_in[14];
    const float* Wl    = (const float*)d_in[15];
    const float* bl    = (const float*)d_in[16];
    const float* Wg    = (const float*)d_in[17];
    const float* bg    = (const float*)d_in[18];
    float* out = (float*)d_out;

    bf16*  pW0i = (bf16*)sym(g_W0i);
    bf16*  pW1i = (bf16*)sym(g_W1i);
    bf16*  pWaT = (bf16*)sym(g_WaT);
    bf16*  pWlz = (bf16*)sym(g_Wlz);
    bf16*  pWlc = (bf16*)sym(g_Wlc);
    bf16*  pWg  = (bf16*)sym(g_Wg);
    bf16*  pEs  = (bf16*)sym(g_eseq);
    bf16*  pXe  = (bf16*)sym(g_xe);
    bf16*  pXa  = (bf16*)sym(g_xa);
    bf16*  pXc  = (bf16*)sym(g_xc);
    bf16*  pOuts= (bf16*)sym(g_outs);
    float* pB0i = (float*)sym(g_b0i);
    float* pB1i = (float*)sym(g_b1i);
    float* pBad = (float*)sym(g_badot);

    static bool attr_done = false;
    if (!attr_done) {
        cudaFuncSetAttribute(k_recur, cudaFuncAttributeMaxDynamicSharedMemorySize,
                             SMEM_RECUR);
        attr_done = true;
    }

    // ---- precompute (loop-invariant) ----
    {
        int n;
        n = 4096 * 2560; k_cvt_w0_i<<<(n + 255) / 256, 256>>>(pW0i, Wih0, Whh0);
        n = 4096 * 2048; k_cvt_w1_i<<<(n + 255) / 256, 256>>>(pW1i, Wih1, Whh1);
        n = 1024 * 1024;
        k_cvt_T<<<(n + 255) / 256, 256>>>(pWaT, Wa);
        k_cvt_slice<<<(n + 255) / 256, 256>>>(pWlz, Wl, 2048, 0, 1024, 1024);
        k_cvt_slice<<<(n + 255) / 256, 256>>>(pWlc, Wl, 2048, 1024, 1024, 1024);
        n = 32000 * 1024; k_cvt<<<(n + 255) / 256, 256>>>(pWg, Wg, n);
        n = 2048 * 1024;  k_cvt<<<(n + 255) / 256, 256>>>(pXe, x_enc, n);
        k_addb_i<<<16, 256>>>(pB0i, bih0, bhh0);
        k_addb_i<<<16, 256>>>(pB1i, bih1, bhh1);
        n = NSTEP * NB * 512; k_embed<<<(n + 255) / 256, 256>>>(pEs, x, emb);
        k_init<<<128, 256>>>(h0in, c0in);
        k_badot<<<256, 256>>>(ba, x_enc, pBad);
        // xa = x_enc @ Wa   (via WaT), xc = x_enc @ Wlc^T
        k_gemm_big<<<dim3(8, 16), 256>>>(pXe, pWaT, pXa, 1024, 1024);
        k_gemm_big<<<dim3(8, 16), 256>>>(pXe, pWlc, pXc, 1024, 1024);
    }

    // ---- full recurrence: ONE persistent kernel ----
    k_recur<<<GRID_P, 256, SMEM_RECUR>>>(bl);

    // ---- generator + log_softmax ----
    k_gen<<<dim3(250, 8), 256>>>(pOuts + NB * HH, pWg, bg, out);
    k_lsm<<<NSTEP * NB, 256>>>(out);

    (void)in_sizes; (void)n_in; (void)out_size;
}

// round 5
// speedup vs baseline: 3.8373x; 1.0759x over previous
#include <cuda_runtime.h>
#include <cuda_bf16.h>
#include <cstdint>

typedef __nv_bfloat16 bf16;

#define NB 32
#define TT 64
#define NSTEP 63
#define HH 1024
#define VV 32000
#define GRID_P 148

// ---------------- static scratch --------------------------------------------
__device__ __align__(16) bf16 g_W0r[4096 * 2048];   // [Wih0[:,512:]|Whh0] rows interleaved 4u+g
__device__ __align__(16) bf16 g_W0e[4096 * 512];    // Wih0[:,:512] interleaved rows
__device__ __align__(16) bf16 g_W1i[4096 * 2048];   // [Wih1|Whh1] interleaved rows
__device__ __align__(16) bf16 g_WaT[1024 * 1024];
__device__ __align__(16) bf16 g_Wlz[1024 * 1024];
__device__ __align__(16) bf16 g_Wlc[1024 * 1024];
__device__ __align__(16) bf16 g_Wg [32000 * 1024];
__device__ __align__(16) bf16 g_eseq[2048 * 512];
__device__ __align__(16) float g_eg [2048 * 4096];  // e@W0e^T + b0 (interleaved cols)
__device__ __align__(16) bf16 g_xe[2048 * 1024];
__device__ __align__(16) bf16 g_xa[2048 * 1024];
__device__ __align__(16) bf16 g_xc[2048 * 1024];
__device__ __align__(16) bf16 g_outs[2080 * 1024];  // slot 1+t = out_t; slot0 zeros
__device__ float g_b0i[4096];
__device__ float g_b1i[4096];
__device__ __align__(16) bf16 g_h0buf[2 * NB * HH];
__device__ __align__(16) bf16 g_h1buf[2 * NB * HH];
__device__ float g_c0[NB * HH];
__device__ float g_c1[NB * HH];
__device__ float g_ctxl[NB * HH];
__device__ float g_wl[NB * HH];
__device__ float g_badot[2048];
__device__ unsigned long long g_bar_cnt;
__device__ unsigned long long g_bar_gen;

// ---------------- helpers ----------------------------------------------------
__device__ __forceinline__ uint32_t smem_u32(const void* p) {
    return (uint32_t)__cvta_generic_to_shared(p);
}
__device__ __forceinline__ void ldsm4(uint32_t addr, uint32_t& r0, uint32_t& r1,
                                      uint32_t& r2, uint32_t& r3) {
    asm volatile("ldmatrix.sync.aligned.m8n8.x4.shared.b16 {%0,%1,%2,%3}, [%4];"
                 : "=r"(r0), "=r"(r1), "=r"(r2), "=r"(r3) : "r"(addr));
}
__device__ __forceinline__ void mma16816(float* c, uint32_t a0, uint32_t a1,
                                         uint32_t a2, uint32_t a3,
                                         uint32_t b0, uint32_t b1) {
    asm volatile(
        "mma.sync.aligned.m16n8k16.row.col.f32.bf16.bf16.f32 "
        "{%0,%1,%2,%3},{%4,%5,%6,%7},{%8,%9},{%0,%1,%2,%3};"
        : "+f"(c[0]), "+f"(c[1]), "+f"(c[2]), "+f"(c[3])
        : "r"(a0), "r"(a1), "r"(a2), "r"(a3), "r"(b0), "r"(b1));
}
__device__ __forceinline__ float sigmoidf_(float x) { return 1.f / (1.f + expf(-x)); }
__device__ __forceinline__ void cpa16(void* dst, const void* src) {
    asm volatile("cp.async.cg.shared.global [%0], [%1], 16;"
                 :: "r"(smem_u32(dst)), "l"(src));
}
__device__ __forceinline__ uint4 pack8(float4 a, float4 b) {
    uint4 o;
    __nv_bfloat162 p;
    p = __floats2bfloat162_rn(a.x, a.y); o.x = *(uint32_t*)&p;
    p = __floats2bfloat162_rn(a.z, a.w); o.y = *(uint32_t*)&p;
    p = __floats2bfloat162_rn(b.x, b.y); o.z = *(uint32_t*)&p;
    p = __floats2bfloat162_rn(b.z, b.w); o.w = *(uint32_t*)&p;
    return o;
}

// grid-wide barrier (monotonic, graph-replay safe)
__device__ __forceinline__ void gbar() {
    __syncthreads();
    if (threadIdx.x == 0) {
        __threadfence();
        unsigned long long arrive = atomicAdd(&g_bar_cnt, 1ULL);
        unsigned long long target = arrive / GRID_P + 1ULL;
        if ((arrive % GRID_P) == GRID_P - 1) {
            atomicAdd(&g_bar_gen, 1ULL);
        } else {
            unsigned long long g;
            do {
                __nanosleep(32);
                asm volatile("ld.acquire.gpu.global.u64 %0, [%1];"
                             : "=l"(g) : "l"(&g_bar_gen));
            } while (g < target);
        }
        __threadfence();
    }
    __syncthreads();
}

// ---------------- vectorized conversion kernels ------------------------------
__global__ void k_cvt8(bf16* dst, const float* src, int n8) {
    int i = blockIdx.x * blockDim.x + threadIdx.x;
    if (i < n8) {
        const float4* s = (const float4*)src + (size_t)i * 2;
        ((uint4*)dst)[i] = pack8(s[0], s[1]);
    }
}
__global__ void k_cvt_w0r_i8(bf16* dst, const float* Wih0, const float* Whh0) {
    int i = blockIdx.x * blockDim.x + threadIdx.x;   // 4096*256
    if (i < 4096 * 256) {
        int rn = i >> 8, c8 = (i & 255) * 8;
        int srow = (rn & 3) * 1024 + (rn >> 2);
        const float* s = (c8 < 1024) ? (Wih0 + (size_t)srow * 1536 + 512 + c8)
                                     : (Whh0 + (size_t)srow * 1024 + (c8 - 1024));
        ((uint4*)dst)[i] = pack8(((const float4*)s)[0], ((const float4*)s)[1]);
    }
}
__global__ void k_cvt_w0e_i8(bf16* dst, const float* Wih0) {
    int i = blockIdx.x * blockDim.x + threadIdx.x;   // 4096*64
    if (i < 4096 * 64) {
        int rn = i >> 6, c8 = (i & 63) * 8;
        int srow = (rn & 3) * 1024 + (rn >> 2);
        const float* s = Wih0 + (size_t)srow * 1536 + c8;
        ((uint4*)dst)[i] = pack8(((const float4*)s)[0], ((const float4*)s)[1]);
    }
}
__global__ void k_cvt_w1_i8(bf16* dst, const float* Wih1, const float* Whh1) {
    int i = blockIdx.x * blockDim.x + threadIdx.x;   // 4096*256
    if (i < 4096 * 256) {
        int rn = i >> 8, c8 = (i & 255) * 8;
        int srow = (rn & 3) * 1024 + (rn >> 2);
        const float* s = (c8 < 1024) ? (Wih1 + (size_t)srow * 1024 + c8)
                                     : (Whh1 + (size_t)srow * 1024 + (c8 - 1024));
        ((uint4*)dst)[i] = pack8(((const float4*)s)[0], ((const float4*)s)[1]);
    }
}
__global__ void k_cvt_slice8(bf16* dst, const float* src, int strideS, int off,
                             int w8, int n8) {
    int i = blockIdx.x * blockDim.x + threadIdx.x;
    if (i < n8) {
        int r = i / w8, c8 = (i % w8) * 8;
        const float* s = src + (size_t)r * strideS + off + c8;
        ((uint4*)dst)[i] = pack8(((const float4*)s)[0], ((const float4*)s)[1]);
    }
}
__global__ void k_cvt_T(bf16* dst, const float* src) {   // 1024x1024 transpose
    int i = blockIdx.x * blockDim.x + threadIdx.x;
    if (i < 1024 * 1024) {
        int n = i >> 10, h = i & 1023;
        dst[i] = __float2bfloat16(src[h * 1024 + n]);
    }
}
__global__ void k_addb_i(float* dst, const float* a, const float* b) {
    int i = blockIdx.x * blockDim.x + threadIdx.x;
    if (i < 4096) {
        int u = i >> 2, g = i & 3;
        dst[i] = a[g * 1024 + u] + b[g * 1024 + u];
    }
}
__global__ void k_embed8(bf16* eseq, const int* x, const float* emb) {
    int i = blockIdx.x * blockDim.x + threadIdx.x;   // 2016*64
    if (i < NSTEP * NB * 64) {
        int c8 = (i & 63) * 8;
        int m = i >> 6;
        int b = m & 31, t = m >> 5;
        int tok = x[b * TT + t];
        const float* s = emb + (size_t)tok * 512 + c8;
        ((uint4*)eseq)[i] = pack8(((const float4*)s)[0], ((const float4*)s)[1]);
    }
}
__global__ void k_init(const float* h0in, const float* c0in) {
    int i = blockIdx.x * blockDim.x + threadIdx.x;
    if (i < NB * HH) {
        g_h0buf[i] = __float2bfloat16(h0in[i]);
        g_h1buf[i] = __float2bfloat16(h0in[NB * HH + i]);
        g_c0[i] = c0in[i];
        g_c1[i] = c0in[NB * HH + i];
    }
}
__global__ void k_badot(const float* ba, const float* x_enc, float* badot) {
    int warp = threadIdx.x >> 5, lane = threadIdx.x & 31;
    int row = blockIdx.x * 8 + warp;
    const float* xr = x_enc + (size_t)row * 1024;
    float s = 0.f;
    for (int h = lane; h < 1024; h += 32) s += ba[h] * xr[h];
#pragma unroll
    for (int o = 16; o; o >>= 1) s += __shfl_xor_sync(0xffffffffu, s, o);
    if (lane == 0) badot[row] = s;
}

// ---------------- generic 128x128 GEMM (precompute) --------------------------
// mode 0: Cf = A@W^T + bias (fp32). mode 1: Cb = A@W^T (bf16)
__global__ void __launch_bounds__(256) k_gemm_big(
    const bf16* __restrict__ A, const bf16* __restrict__ W,
    const float* __restrict__ bias, float* __restrict__ Cf, bf16* __restrict__ Cb,
    int N, int K, int mode)
{
    __shared__ __align__(16) bf16 As[128 * 40];
    __shared__ __align__(16) bf16 Bs[128 * 40];
    const int tid = threadIdx.x, warp = tid >> 5, lane = tid & 31;
    const int wr = warp >> 2, wc = warp & 3;
    const int mblk = blockIdx.y * 128;
    const int nblk = blockIdx.x * 128;
    const int sub = lane >> 3, ri = lane & 7;

    float acc[4][4][4];
#pragma unroll
    for (int a = 0; a < 4; a++)
#pragma unroll
        for (int b = 0; b < 4; b++)
#pragma unroll
            for (int c = 0; c < 4; c++) acc[a][b][c] = 0.f;

    for (int kb = 0; kb < K; kb += 32) {
        __syncthreads();
#pragma unroll
        for (int i = 0; i < 4; i++) {
            int v = tid + i * 256;
            if (v < 512) {
                int m = v >> 2, cv = v & 3;
                *(uint4*)&As[m * 40 + cv * 8] =
                    *(const uint4*)(A + (size_t)(mblk + m) * K + kb + cv * 8);
            } else {
                int u = v - 512;
                int n = u >> 2, cv = u & 3;
                *(uint4*)&Bs[n * 40 + cv * 8] =
                    *(const uint4*)(W + (size_t)(nblk + n) * K + kb + cv * 8);
            }
        }
        __syncthreads();
#pragma unroll
        for (int kk = 0; kk < 32; kk += 16) {
            uint32_t a[4][4], b[4][2];
#pragma unroll
            for (int mt = 0; mt < 4; mt++) {
                int row = wr * 64 + mt * 16 + (sub & 1) * 8 + ri;
                int col = kk + (sub >> 1) * 8;
                ldsm4(smem_u32(&As[row * 40 + col]), a[mt][0], a[mt][1], a[mt][2], a[mt][3]);
            }
#pragma unroll
            for (int ntp = 0; ntp < 2; ntp++) {
                int row = wc * 32 + ntp * 16 + (sub >> 1) * 8 + ri;
                int col = kk + (sub & 1) * 8;
                ldsm4(smem_u32(&Bs[row * 40 + col]),
                      b[ntp * 2][0], b[ntp * 2][1], b[ntp * 2 + 1][0], b[ntp * 2 + 1][1]);
            }
#pragma unroll
            for (int mt = 0; mt < 4; mt++)
#pragma unroll
                for (int nt = 0; nt < 4; nt++)
                    mma16816(acc[mt][nt], a[mt][0], a[mt][1], a[mt][2], a[mt][3],
                             b[nt][0], b[nt][1]);
        }
    }

    const int r0 = lane >> 2, c0 = (lane & 3) * 2;
#pragma unroll
    for (int mt = 0; mt < 4; mt++)
#pragma unroll
        for (int nt = 0; nt < 4; nt++) {
            int n = nblk + wc * 32 + nt * 8 + c0;
#pragma unroll
            for (int half = 0; half < 2; half++) {
                int m = mblk + wr * 64 + mt * 16 + r0 + half * 8;
                float v0 = acc[mt][nt][half * 2 + 0];
                float v1 = acc[mt][nt][half * 2 + 1];
                if (mode == 0) {
                    Cf[(size_t)m * N + n]     = v0 + bias[n];
                    Cf[(size_t)m * N + n + 1] = v1 + bias[n + 1];
                } else {
                    Cb[(size_t)m * N + n]     = __float2bfloat16(v0);
                    Cb[(size_t)m * N + n + 1] = __float2bfloat16(v1);
                }
            }
        }
}

// ---------------- persistent-kernel step GEMM (cp.async pipelined) -----------
// SMEM layout (dynamic): As0 @0, Ws0 @33280, As1 @66560, Ws1 @99840, red @133120
#define SMOFF_AS0 0
#define SMOFF_WS0 33280
#define SMOFF_AS1 66560
#define SMOFF_WS1 99840
#define SMOFF_RED 133120
#define SMEM_RECUR (133120 + 8 * 32 * 33 * 4)   // 166912

__device__ __forceinline__ void issue_chunk(char* smraw, int buf,
    const bf16* Asrc, int ast, const bf16* Wsrc, int wst) {
    bf16* As = (bf16*)(smraw + (buf ? SMOFF_AS1 : SMOFF_AS0));
    bf16* Ws = (bf16*)(smraw + (buf ? SMOFF_WS1 : SMOFF_WS0));
    const int tid = threadIdx.x;
#pragma unroll
    for (int i = 0; i < 8; i++) {
        int v = tid + i * 256;
        int r = v >> 6, c = v & 63;
        cpa16(&As[r * 520 + c * 8], Asrc + (size_t)r * ast + c * 8);
    }
#pragma unroll
    for (int i = 0; i < 8; i++) {
        int v = tid + i * 256;
        int r = v >> 6, c = v & 63;
        cpa16(&Ws[r * 520 + c * 8], Wsrc + (size_t)r * wst + c * 8);
    }
    asm volatile("cp.async.commit_group;");
}

__device__ __forceinline__ void compute_chunk(char* smraw, int buf,
                                              float acc[2][4][4]) {
    bf16* As = (bf16*)(smraw + (buf ? SMOFF_AS1 : SMOFF_AS0));
    bf16* Ws = (bf16*)(smraw + (buf ? SMOFF_WS1 : SMOFF_WS0));
    const int warp = threadIdx.x >> 5, lane = threadIdx.x & 31;
    const int sub = lane >> 3, ri = lane & 7;
#pragma unroll
    for (int kk = 0; kk < 64; kk += 16) {
        int col = (warp << 6) + kk;
        uint32_t a[2][4], b[4][2];
#pragma unroll
        for (int mt = 0; mt < 2; mt++) {
            int row = mt * 16 + (sub & 1) * 8 + ri;
            ldsm4(smem_u32(&As[row * 520 + col + (sub >> 1) * 8]),
                  a[mt][0], a[mt][1], a[mt][2], a[mt][3]);
        }
#pragma unroll
        for (int ntp = 0; ntp < 2; ntp++) {
            int row = ntp * 16 + (sub >> 1) * 8 + ri;
            ldsm4(smem_u32(&Ws[row * 520 + col + (sub & 1) * 8]),
                  b[ntp * 2][0], b[ntp * 2][1], b[ntp * 2 + 1][0], b[ntp * 2 + 1][1]);
        }
#pragma unroll
        for (int mt = 0; mt < 2; mt++)
#pragma unroll
            for (int nt = 0; nt < 4; nt++)
                mma16816(acc[mt][nt], a[mt][0], a[mt][1], a[mt][2], a[mt][3],
                         b[nt][0], b[nt][1]);
    }
}

// C[32, 32cols] = A[32, Kw] @ W[nblk.., Kw]^T; A = [A0 | A1] split at k1.
__device__ void gemm32p(const bf16* __restrict__ A0, int st0,
                        const bf16* __restrict__ A1, int st1,
                        int k1, int Kw,
                        const bf16* __restrict__ W, int nblk,
                        char* smraw, float out[4])
{
    const int tid = threadIdx.x, warp = tid >> 5, lane = tid & 31;
    float acc[2][4][4];
#pragma unroll
    for (int a = 0; a < 2; a++)
#pragma unroll
        for (int b = 0; b < 4; b++)
#pragma unroll
            for (int c = 0; c < 4; c++) acc[a][b][c] = 0.f;

    const int nch = Kw >> 9;
    const bf16* Wb = W + (size_t)nblk * Kw;

    // prologue: chunk 0
    {
        const bf16* Asrc = (0 < k1) ? A0 : A1;
        issue_chunk(smraw, 0, Asrc, (0 < k1) ? st0 : st1, Wb, Kw);
    }
    for (int ch = 0; ch < nch; ch++) {
        __syncthreads();                      // prior compute done
        if (ch + 1 < nch) {
            int k0 = (ch + 1) << 9;
            const bf16* Asrc; int ast;
            if (k0 < k1) { Asrc = A0 + k0; ast = st0; }
            else         { Asrc = A1 + (k0 - k1); ast = st1; }
            issue_chunk(smraw, (ch + 1) & 1, Asrc, ast, Wb + k0, Kw);
            asm volatile("cp.async.wait_group 1;");
        } else {
            asm volatile("cp.async.wait_group 0;");
        }
        __syncthreads();                      // chunk ch visible
        compute_chunk(smraw, ch & 1, acc);
    }

    // cross-warp reduction
    float* red = (float*)(smraw + SMOFF_RED);
    __syncthreads();
    float* rw = red + warp * (32 * 33);
#pragma unroll
    for (int mt = 0; mt < 2; mt++)
#pragma unroll
        for (int nt = 0; nt < 4; nt++) {
            int m = mt * 16 + (lane >> 2);
            int n0 = nt * 8 + (lane & 3) * 2;
            rw[m * 33 + n0]           = acc[mt][nt][0];
            rw[m * 33 + n0 + 1]       = acc[mt][nt][1];
            rw[(m + 8) * 33 + n0]     = acc[mt][nt][2];
            rw[(m + 8) * 33 + n0 + 1] = acc[mt][nt][3];
        }
    __syncthreads();
    int b = tid >> 3, ul = tid & 7;
#pragma unroll
    for (int g = 0; g < 4; g++) {
        float s = 0.f;
#pragma unroll
        for (int w = 0; w < 8; w++) s += red[w * (32 * 33) + b * 33 + ul * 4 + g];
        out[g] = s;
    }
}

// ---------------- attention (device func) ------------------------------------
__device__ void attn_dev(int b, const bf16* __restrict__ h1, char* smraw) {
    float* h1s = (float*)smraw;
    float* sc = h1s + 1024;
    int tid = threadIdx.x;
    for (int u = tid; u < 1024; u += 256) h1s[u] = __bfloat162float(h1[b * 1024 + u]);
    __syncthreads();
    int warp = tid >> 5, lane = tid & 31;
#pragma unroll
    for (int jj = 0; jj < 8; jj++) {
        int j = warp * 8 + jj;
        const uint4* xr = (const uint4*)(g_xa + (size_t)(b * 64 + j) * 1024);
        float s = 0.f;
        for (int k4 = lane; k4 < 128; k4 += 32) {
            uint4 v = xr[k4];
            const __nv_bfloat162* p2 = (const __nv_bfloat162*)&v;
            int base = k4 * 8;
#pragma unroll
            for (int q = 0; q < 4; q++) {
                float2 f = __bfloat1622float2(p2[q]);
                s += h1s[base + q * 2] * f.x + h1s[base + q * 2 + 1] * f.y;
            }
        }
#pragma unroll
        for (int o = 16; o; o >>= 1) s += __shfl_xor_sync(0xffffffffu, s, o);
        if (lane == 0) sc[j] = s + g_badot[b * 64 + j];
    }
    __syncthreads();
    if (warp == 0) {
        float v0 = sc[lane], v1 = sc[lane + 32];
        float m = fmaxf(v0, v1);
#pragma unroll
        for (int o = 16; o; o >>= 1) m = fmaxf(m, __shfl_xor_sync(0xffffffffu, m, o));
        float e0 = expf(v0 - m), e1 = expf(v1 - m);
        float s = e0 + e1;
#pragma unroll
        for (int o = 16; o; o >>= 1) s += __shfl_xor_sync(0xffffffffu, s, o);
        sc[lane] = e0 / s;
        sc[lane + 32] = e1 / s;
    }
    __syncthreads();
    for (int n = tid; n < 1024; n += 256) {
        float a = 0.f;
#pragma unroll 8
        for (int j = 0; j < 64; j++)
            a += sc[j] * __bfloat162float(g_xc[(size_t)(b * 64 + j) * 1024 + n]);
        g_ctxl[b * 1024 + n] = a;
    }
}

// ---------------- persistent recurrence kernel -------------------------------
__global__ void __launch_bounds__(256) k_recur(const float* __restrict__ bl) {
    extern __shared__ char smraw[];
    const int bid = blockIdx.x;
    const int tid = threadIdx.x;

    for (int t = 0; t < NSTEP; t++) {
        const bf16* h0_in  = g_h0buf + (t & 1) * (NB * HH);
        bf16*       h0_out = g_h0buf + ((t + 1) & 1) * (NB * HH);
        const bf16* h1_in  = g_h1buf + (t & 1) * (NB * HH);
        bf16*       h1_out = g_h1buf + ((t + 1) & 1) * (NB * HH);
        const bf16* prev   = g_outs + (size_t)t * (NB * HH);

        // P1: layer-0 gates + cell (K = 2048 = [prev | h0]; e-part from eg)
        if (bid < 128) {
            float s[4];
            gemm32p(prev, 1024, h0_in, 1024, 1024, 2048, g_W0r, bid * 32, smraw, s);
            const float* egp = g_eg + ((size_t)t * 32) * 4096;
            int b = tid >> 3, ul = tid & 7;
            int rn = bid * 32 + ul * 4;
            int u = rn >> 2;
            float ig = s[0] + egp[b * 4096 + rn];
            float fg = s[1] + egp[b * 4096 + rn + 1];
            float gg = s[2] + egp[b * 4096 + rn + 2];
            float og = s[3] + egp[b * 4096 + rn + 3];
            float cn = sigmoidf_(fg) * g_c0[b * 1024 + u] + sigmoidf_(ig) * tanhf(gg);
            g_c0[b * 1024 + u] = cn;
            h0_out[b * 1024 + u] = __float2bfloat16(sigmoidf_(og) * tanhf(cn));
        }
        gbar();

        // P2: layer-1 gates + cell (K = 2048 = [h0_new | h1_prev])
        if (bid < 128) {
            float s[4];
            gemm32p(h0_out, 1024, h1_in, 1024, 1024, 2048, g_W1i, bid * 32, smraw, s);
            int b = tid >> 3, ul = tid & 7;
            int rn = bid * 32 + ul * 4;
            int u = rn >> 2;
            float ig = s[0] + g_b1i[rn];
            float fg = s[1] + g_b1i[rn + 1];
            float gg = s[2] + g_b1i[rn + 2];
            float og = s[3] + g_b1i[rn + 3];
            float cn = sigmoidf_(fg) * g_c1[b * 1024 + u] + sigmoidf_(ig) * tanhf(gg);
            g_c1[b * 1024 + u] = cn;
            h1_out[b * 1024 + u] = __float2bfloat16(sigmoidf_(og) * tanhf(cn));
        }
        gbar();

        // P3: attention (blocks 0-31) || z @ Wlz^T (blocks 32-63)
        if (bid < 32) {
            attn_dev(bid, h1_out, smraw);
        } else if (bid < 64) {
            float s[4];
            gemm32p(h1_out, 1024, h1_out, 1024, 1024, 1024,
                    g_Wlz, (bid - 32) * 32, smraw, s);
            int b = tid >> 3, ul = tid & 7;
            int n = (bid - 32) * 32 + ul * 4;
#pragma unroll
            for (int g = 0; g < 4; g++) g_wl[b * 1024 + n + g] = s[g];
        }
        gbar();

        // P4: out = tanh(wl + bl + ctx) -> outs slot t+1 (bf16)
        if (bid < 32) {
            bf16* outt = g_outs + (size_t)(t + 1) * (NB * HH) + bid * 1024;
            int n = tid * 4;
#pragma unroll
            for (int j = 0; j < 4; j++) {
                float v = g_wl[bid * 1024 + n + j] + bl[n + j] + g_ctxl[bid * 1024 + n + j];
                outt[n + j] = __float2bfloat16(tanhf(v));
            }
        }
        gbar();
    }
}

// ---------------- generator GEMM 256x128 tiles --------------------------------
__global__ void __launch_bounds__(256) k_gen(const bf16* __restrict__ A,
                                             const bf16* __restrict__ W,
                                             const float* __restrict__ bias,
                                             float* __restrict__ out) {
    __shared__ __align__(16) bf16 As[256 * 40];
    __shared__ __align__(16) bf16 Ws[128 * 40];
    const int tid = threadIdx.x, warp = tid >> 5, lane = tid & 31;
    const int wr = warp >> 1, wc = warp & 1;
    const int mblk = blockIdx.y * 256;
    const int nblk = blockIdx.x * 128;
    const int sub = lane >> 3, ri = lane & 7;

    float acc[4][8][4];
#pragma unroll
    for (int a = 0; a < 4; a++)
#pragma unroll
        for (int b = 0; b < 8; b++)
#pragma unroll
            for (int c = 0; c < 4; c++) acc[a][b][c] = 0.f;

    for (int kb = 0; kb < 1024; kb += 32) {
        __syncthreads();
#pragma unroll
        for (int i = 0; i < 6; i++) {
            int v = tid + i * 256;
            if (v < 1024) {
                int m = v >> 2, cv = v & 3;
                *(uint4*)&As[m * 40 + cv * 8] =
                    *(const uint4*)(A + (size_t)(mblk + m) * 1024 + kb + cv * 8);
            } else {
                int u = v - 1024;
                int n = u >> 2, cv = u & 3;
                *(uint4*)&Ws[n * 40 + cv * 8] =
                    *(const uint4*)(W + (size_t)(nblk + n) * 1024 + kb + cv * 8);
            }
        }
        __syncthreads();
#pragma unroll
        for (int kk = 0; kk < 32; kk += 16) {
            uint32_t a[4][4], b[8][2];
#pragma unroll
            for (int mt = 0; mt < 4; mt++) {
                int row = wr * 64 + mt * 16 + (sub & 1) * 8 + ri;
                int col = kk + (sub >> 1) * 8;
                ldsm4(smem_u32(&As[row * 40 + col]), a[mt][0], a[mt][1], a[mt][2], a[mt][3]);
            }
#pragma unroll
            for (int ntp = 0; ntp < 4; ntp++) {
                int row = wc * 64 + ntp * 16 + (sub >> 1) * 8 + ri;
                int col = kk + (sub & 1) * 8;
                ldsm4(smem_u32(&Ws[row * 40 + col]),
                      b[ntp * 2][0], b[ntp * 2][1], b[ntp * 2 + 1][0], b[ntp * 2 + 1][1]);
            }
#pragma unroll
            for (int mt = 0; mt < 4; mt++)
#pragma unroll
                for (int nt = 0; nt < 8; nt++)
                    mma16816(acc[mt][nt], a[mt][0], a[mt][1], a[mt][2], a[mt][3],
                             b[nt][0], b[nt][1]);
        }
    }

    const int r0 = lane >> 2, c0 = (lane & 3) * 2;
#pragma unroll
    for (int mt = 0; mt < 4; mt++)
#pragma unroll
        for (int nt = 0; nt < 8; nt++) {
            int n = nblk + wc * 64 + nt * 8 + c0;
            float bv0 = bias[n], bv1 = bias[n + 1];
#pragma unroll
            for (int half = 0; half < 2; half++) {
                int m = mblk + wr * 64 + mt * 16 + r0 + half * 8;
                if (m < NSTEP * NB) {
                    int t = m >> 5, bb = m & 31;
                    size_t orow = (size_t)(bb * NSTEP + t) * VV;
                    out[orow + n]     = acc[mt][nt][half * 2 + 0] + bv0;
                    out[orow + n + 1] = acc[mt][nt][half * 2 + 1] + bv1;
                }
            }
        }
}

// ---------------- log_softmax (vectorized, in place) --------------------------
__global__ void __launch_bounds__(256) k_lsm(float* __restrict__ out) {
    int row = blockIdx.x;
    float4* p = (float4*)(out + (size_t)row * VV);
    __shared__ float red[256];
    int tid = threadIdx.x;
    float m = -1e30f;
    for (int i = tid; i < 8000; i += 256) {
        float4 v = p[i];
        m = fmaxf(m, fmaxf(fmaxf(v.x, v.y), fmaxf(v.z, v.w)));
    }
    red[tid] = m;
    __syncthreads();
    for (int s = 128; s; s >>= 1) {
        if (tid < s) red[tid] = fmaxf(red[tid], red[tid + s]);
        __syncthreads();
    }
    m = red[0];
    __syncthreads();
    float sum = 0.f;
    for (int i = tid; i < 8000; i += 256) {
        float4 v = p[i];
        sum += expf(v.x - m) + expf(v.y - m) + expf(v.z - m) + expf(v.w - m);
    }
    red[tid] = sum;
    __syncthreads();
    for (int s = 128; s; s >>= 1) {
        if (tid < s) red[tid] += red[tid + s];
        __syncthreads();
    }
    float lse = m + logf(red[0]);
    for (int i = tid; i < 8000; i += 256) {
        float4 v = p[i];
        v.x -= lse; v.y -= lse; v.z -= lse; v.w -= lse;
        p[i] = v;
    }
}

// ---------------- host ---------------------------------------------------------
static void* sym(const void* s) {
    void* p = nullptr;
    cudaGetSymbolAddress(&p, s);
    return p;
}

extern "C" void kernel_launch(void* const* d_in, const int* in_sizes, int n_in,
                              void* d_out, int out_size) {
    const int*   x     = (const int*)d_in[0];
    const float* h0in  = (const float*)d_in[1];
    const float* c0in  = (const float*)d_in[2];
    const float* x_enc = (const float*)d_in[3];
    const float* emb   = (const float*)d_in[4];
    const float* Wih0  = (const float*)d_in[5];
    const float* Whh0  = (const float*)d_in[6];
    const float* bih0  = (const float*)d_in[7];
    const float* bhh0  = (const float*)d_in[8];
    const float* Wih1  = (const float*)d_in[9];
    const float* Whh1  = (const float*)d_in[10];
    const float* bih1  = (const float*)d_in[11];
    const float* bhh1  = (const float*)d_in[12];
    const float* Wa    = (const float*)d_in[13];
    const float* ba    = (const float*)d_in[14];
    const float* Wl    = (const float*)d_in[15];
    const float* bl    = (const float*)d_in[16];
    const float* Wg    = (const float*)d_in[17];
    const float* bg    = (const float*)d_in[18];
    float* out = (float*)d_out;

    bf16*  pW0r = (bf16*)sym(g_W0r);
    bf16*  pW0e = (bf16*)sym(g_W0e);
    bf16*  pW1i = (bf16*)sym(g_W1i);
    bf16*  pWaT = (bf16*)sym(g_WaT);
    bf16*  pWlz = (bf16*)sym(g_Wlz);
    bf16*  pWlc = (bf16*)sym(g_Wlc);
    bf16*  pWg  = (bf16*)sym(g_Wg);
    bf16*  pEs  = (bf16*)sym(g_eseq);
    float* pEg  = (float*)sym(g_eg);
    bf16*  pXe  = (bf16*)sym(g_xe);
    bf16*  pXa  = (bf16*)sym(g_xa);
    bf16*  pXc  = (bf16*)sym(g_xc);
    bf16*  pOuts= (bf16*)sym(g_outs);
    float* pB0i = (float*)sym(g_b0i);
    float* pB1i = (float*)sym(g_b1i);
    float* pBad = (float*)sym(g_badot);

    static bool attr_done = false;
    if (!attr_done) {
        cudaFuncSetAttribute(k_recur, cudaFuncAttributeMaxDynamicSharedMemorySize,
                             SMEM_RECUR);
        attr_done = true;
    }

    // ---- precompute (vectorized conversions + loop-invariant GEMMs) ----
    {
        int n8;
        n8 = 4096 * 256; k_cvt_w0r_i8<<<(n8 + 255) / 256, 256>>>(pW0r, Wih0, Whh0);
        n8 = 4096 * 64;  k_cvt_w0e_i8<<<(n8 + 255) / 256, 256>>>(pW0e, Wih0);
        n8 = 4096 * 256; k_cvt_w1_i8<<<(n8 + 255) / 256, 256>>>(pW1i, Wih1, Whh1);
        k_cvt_T<<<4096, 256>>>(pWaT, Wa);
        n8 = 1024 * 128;
        k_cvt_slice8<<<(n8 + 255) / 256, 256>>>(pWlz, Wl, 2048, 0, 128, n8);
        k_cvt_slice8<<<(n8 + 255) / 256, 256>>>(pWlc, Wl, 2048, 1024, 128, n8);
        n8 = 32000 * 128; k_cvt8<<<(n8 + 255) / 256, 256>>>(pWg, Wg, n8);
        n8 = 2048 * 128;  k_cvt8<<<(n8 + 255) / 256, 256>>>(pXe, x_enc, n8);
        k_addb_i<<<16, 256>>>(pB0i, bih0, bhh0);
        k_addb_i<<<16, 256>>>(pB1i, bih1, bhh1);
        n8 = NSTEP * NB * 64; k_embed8<<<(n8 + 255) / 256, 256>>>(pEs, x, emb);
        k_init<<<128, 256>>>(h0in, c0in);
        k_badot<<<256, 256>>>(ba, x_enc, pBad);
        // eg = eseq @ W0e^T + b0i   [2048, 4096] fp32 (interleaved cols)
        k_gemm_big<<<dim3(32, 16), 256>>>(pEs, pW0e, pB0i, pEg, nullptr, 4096, 512, 0);
        // xa = x_enc @ Wa,  xc = x_enc @ Wlc^T  (bf16)
        k_gemm_big<<<dim3(8, 16), 256>>>(pXe, pWaT, nullptr, nullptr, pXa, 1024, 1024, 1);
        k_gemm_big<<<dim3(8, 16), 256>>>(pXe, pWlc, nullptr, nullptr, pXc, 1024, 1024, 1);
    }

    // ---- full recurrence: ONE persistent kernel ----
    k_recur<<<GRID_P, 256, SMEM_RECUR>>>(bl);

    // ---- generator + log_softmax ----
    k_gen<<<dim3(250, 8), 256>>>(pOuts + NB * HH, pWg, bg, out);
    k_lsm<<<NSTEP * NB, 256>>>(out);

    (void)in_sizes; (void)n_in; (void)out_size;
}

// round 6
// speedup vs baseline: 3.8682x; 1.0080x over previous
#include <cuda_runtime.h>
#include <cuda_bf16.h>
#include <cstdint>

typedef __nv_bfloat16 bf16;

#define NB 32
#define TT 64
#define NSTEP 63
#define HH 1024
#define VV 32000
#define GRID_P 148

// ---------------- static scratch --------------------------------------------
__device__ __align__(16) bf16 g_W0r[4096 * 2048];   // [Wih0[:,512:]|Whh0] rows interleaved 4u+g
__device__ __align__(16) bf16 g_W0e[4096 * 512];    // Wih0[:,:512] interleaved rows
__device__ __align__(16) bf16 g_W1i[4096 * 2048];   // [Wih1|Whh1] interleaved rows
__device__ __align__(16) bf16 g_WaT[1024 * 1024];
__device__ __align__(16) bf16 g_Wlz[1024 * 1024];
__device__ __align__(16) bf16 g_Wlc[1024 * 1024];
__device__ __align__(16) bf16 g_Wg [32000 * 1024];
__device__ __align__(16) bf16 g_eseq[2048 * 512];
__device__ __align__(16) float g_eg [2048 * 4096];  // e@W0e^T + b0 (interleaved cols)
__device__ __align__(16) bf16 g_xe[2048 * 1024];
__device__ __align__(16) bf16 g_xa[2048 * 1024];
__device__ __align__(16) bf16 g_xc[2048 * 1024];
__device__ __align__(16) bf16 g_outs[2080 * 1024];  // slot 1+t = out_t; slot0 zeros
__device__ float g_b0i[4096];
__device__ float g_b1i[4096];
__device__ __align__(16) bf16 g_h0buf[2 * NB * HH];
__device__ __align__(16) bf16 g_h1buf[2 * NB * HH];
__device__ float g_c0[NB * HH];
__device__ float g_c1[NB * HH];
__device__ float g_ctxl[NB * HH];
__device__ float g_wl[NB * HH];
__device__ float g_badot[2048];
__device__ unsigned long long g_bar_cnt;
__device__ unsigned long long g_bar_gen;

// ---------------- helpers ----------------------------------------------------
__device__ __forceinline__ uint32_t smem_u32(const void* p) {
    return (uint32_t)__cvta_generic_to_shared(p);
}
__device__ __forceinline__ void ldsm4(uint32_t addr, uint32_t& r0, uint32_t& r1,
                                      uint32_t& r2, uint32_t& r3) {
    asm volatile("ldmatrix.sync.aligned.m8n8.x4.shared.b16 {%0,%1,%2,%3}, [%4];"
                 : "=r"(r0), "=r"(r1), "=r"(r2), "=r"(r3) : "r"(addr));
}
__device__ __forceinline__ void mma16816(float* c, uint32_t a0, uint32_t a1,
                                         uint32_t a2, uint32_t a3,
                                         uint32_t b0, uint32_t b1) {
    asm volatile(
        "mma.sync.aligned.m16n8k16.row.col.f32.bf16.bf16.f32 "
        "{%0,%1,%2,%3},{%4,%5,%6,%7},{%8,%9},{%0,%1,%2,%3};"
        : "+f"(c[0]), "+f"(c[1]), "+f"(c[2]), "+f"(c[3])
        : "r"(a0), "r"(a1), "r"(a2), "r"(a3), "r"(b0), "r"(b1));
}
__device__ __forceinline__ float sigmoidf_(float x) { return 1.f / (1.f + expf(-x)); }
__device__ __forceinline__ void cpa16(void* dst, const void* src) {
    asm volatile("cp.async.cg.shared.global [%0], [%1], 16;"
                 :: "r"(smem_u32(dst)), "l"(src));
}
__device__ __forceinline__ uint4 pack8(float4 a, float4 b) {
    uint4 o;
    __nv_bfloat162 p;
    p = __floats2bfloat162_rn(a.x, a.y); o.x = *(uint32_t*)&p;
    p = __floats2bfloat162_rn(a.z, a.w); o.y = *(uint32_t*)&p;
    p = __floats2bfloat162_rn(b.x, b.y); o.z = *(uint32_t*)&p;
    p = __floats2bfloat162_rn(b.z, b.w); o.w = *(uint32_t*)&p;
    return o;
}

// grid-wide barrier (monotonic, graph-replay safe)
__device__ __forceinline__ void gbar() {
    __syncthreads();
    if (threadIdx.x == 0) {
        __threadfence();
        unsigned long long arrive = atomicAdd(&g_bar_cnt, 1ULL);
        unsigned long long target = arrive / GRID_P + 1ULL;
        if ((arrive % GRID_P) == GRID_P - 1) {
            atomicAdd(&g_bar_gen, 1ULL);
        } else {
            unsigned long long g;
            do {
                __nanosleep(32);
                asm volatile("ld.acquire.gpu.global.u64 %0, [%1];"
                             : "=l"(g) : "l"(&g_bar_gen));
            } while (g < target);
        }
        __threadfence();
    }
    __syncthreads();
}

// ---------------- vectorized conversion kernels ------------------------------
__global__ void k_cvt8(bf16* dst, const float* src, int n8) {
    int i = blockIdx.x * blockDim.x + threadIdx.x;
    if (i < n8) {
        const float4* s = (const float4*)src + (size_t)i * 2;
        ((uint4*)dst)[i] = pack8(s[0], s[1]);
    }
}
__global__ void k_cvt_w0r_i8(bf16* dst, const float* Wih0, const float* Whh0) {
    int i = blockIdx.x * blockDim.x + threadIdx.x;   // 4096*256
    if (i < 4096 * 256) {
        int rn = i >> 8, c8 = (i & 255) * 8;
        int srow = (rn & 3) * 1024 + (rn >> 2);
        const float* s = (c8 < 1024) ? (Wih0 + (size_t)srow * 1536 + 512 + c8)
                                     : (Whh0 + (size_t)srow * 1024 + (c8 - 1024));
        ((uint4*)dst)[i] = pack8(((const float4*)s)[0], ((const float4*)s)[1]);
    }
}
__global__ void k_cvt_w0e_i8(bf16* dst, const float* Wih0) {
    int i = blockIdx.x * blockDim.x + threadIdx.x;   // 4096*64
    if (i < 4096 * 64) {
        int rn = i >> 6, c8 = (i & 63) * 8;
        int srow = (rn & 3) * 1024 + (rn >> 2);
        const float* s = Wih0 + (size_t)srow * 1536 + c8;
        ((uint4*)dst)[i] = pack8(((const float4*)s)[0], ((const float4*)s)[1]);
    }
}
__global__ void k_cvt_w1_i8(bf16* dst, const float* Wih1, const float* Whh1) {
    int i = blockIdx.x * blockDim.x + threadIdx.x;   // 4096*256
    if (i < 4096 * 256) {
        int rn = i >> 8, c8 = (i & 255) * 8;
        int srow = (rn & 3) * 1024 + (rn >> 2);
        const float* s = (c8 < 1024) ? (Wih1 + (size_t)srow * 1024 + c8)
                                     : (Whh1 + (size_t)srow * 1024 + (c8 - 1024));
        ((uint4*)dst)[i] = pack8(((const float4*)s)[0], ((const float4*)s)[1]);
    }
}
__global__ void k_cvt_slice8(bf16* dst, const float* src, int strideS, int off,
                             int w8, int n8) {
    int i = blockIdx.x * blockDim.x + threadIdx.x;
    if (i < n8) {
        int r = i / w8, c8 = (i % w8) * 8;
        const float* s = src + (size_t)r * strideS + off + c8;
        ((uint4*)dst)[i] = pack8(((const float4*)s)[0], ((const float4*)s)[1]);
    }
}
__global__ void k_cvt_T(bf16* dst, const float* src) {   // 1024x1024 transpose
    int i = blockIdx.x * blockDim.x + threadIdx.x;
    if (i < 1024 * 1024) {
        int n = i >> 10, h = i & 1023;
        dst[i] = __float2bfloat16(src[h * 1024 + n]);
    }
}
__global__ void k_addb_i(float* dst, const float* a, const float* b) {
    int i = blockIdx.x * blockDim.x + threadIdx.x;
    if (i < 4096) {
        int u = i >> 2, g = i & 3;
        dst[i] = a[g * 1024 + u] + b[g * 1024 + u];
    }
}
__global__ void k_embed8(bf16* eseq, const int* x, const float* emb) {
    int i = blockIdx.x * blockDim.x + threadIdx.x;   // 2016*64
    if (i < NSTEP * NB * 64) {
        int c8 = (i & 63) * 8;
        int m = i >> 6;
        int b = m & 31, t = m >> 5;
        int tok = x[b * TT + t];
        const float* s = emb + (size_t)tok * 512 + c8;
        ((uint4*)eseq)[i] = pack8(((const float4*)s)[0], ((const float4*)s)[1]);
    }
}
__global__ void k_init(const float* h0in, const float* c0in) {
    int i = blockIdx.x * blockDim.x + threadIdx.x;
    if (i < NB * HH) {
        g_h0buf[i] = __float2bfloat16(h0in[i]);
        g_h1buf[i] = __float2bfloat16(h0in[NB * HH + i]);
        g_c0[i] = c0in[i];
        g_c1[i] = c0in[NB * HH + i];
    }
}
__global__ void k_badot(const float* ba, const float* x_enc, float* badot) {
    int warp = threadIdx.x >> 5, lane = threadIdx.x & 31;
    int row = blockIdx.x * 8 + warp;
    const float* xr = x_enc + (size_t)row * 1024;
    float s = 0.f;
    for (int h = lane; h < 1024; h += 32) s += ba[h] * xr[h];
#pragma unroll
    for (int o = 16; o; o >>= 1) s += __shfl_xor_sync(0xffffffffu, s, o);
    if (lane == 0) badot[row] = s;
}

// ---------------- generic 128x128 GEMM (precompute) --------------------------
// mode 0: Cf = A@W^T + bias (fp32). mode 1: Cb = A@W^T (bf16)
__global__ void __launch_bounds__(256) k_gemm_big(
    const bf16* __restrict__ A, const bf16* __restrict__ W,
    const float* __restrict__ bias, float* __restrict__ Cf, bf16* __restrict__ Cb,
    int N, int K, int mode)
{
    __shared__ __align__(16) bf16 As[128 * 40];
    __shared__ __align__(16) bf16 Bs[128 * 40];
    const int tid = threadIdx.x, warp = tid >> 5, lane = tid & 31;
    const int wr = warp >> 2, wc = warp & 3;
    const int mblk = blockIdx.y * 128;
    const int nblk = blockIdx.x * 128;
    const int sub = lane >> 3, ri = lane & 7;

    float acc[4][4][4];
#pragma unroll
    for (int a = 0; a < 4; a++)
#pragma unroll
        for (int b = 0; b < 4; b++)
#pragma unroll
            for (int c = 0; c < 4; c++) acc[a][b][c] = 0.f;

    for (int kb = 0; kb < K; kb += 32) {
        __syncthreads();
#pragma unroll
        for (int i = 0; i < 4; i++) {
            int v = tid + i * 256;
            if (v < 512) {
                int m = v >> 2, cv = v & 3;
                *(uint4*)&As[m * 40 + cv * 8] =
                    *(const uint4*)(A + (size_t)(mblk + m) * K + kb + cv * 8);
            } else {
                int u = v - 512;
                int n = u >> 2, cv = u & 3;
                *(uint4*)&Bs[n * 40 + cv * 8] =
                    *(const uint4*)(W + (size_t)(nblk + n) * K + kb + cv * 8);
            }
        }
        __syncthreads();
#pragma unroll
        for (int kk = 0; kk < 32; kk += 16) {
            uint32_t a[4][4], b[4][2];
#pragma unroll
            for (int mt = 0; mt < 4; mt++) {
                int row = wr * 64 + mt * 16 + (sub & 1) * 8 + ri;
                int col = kk + (sub >> 1) * 8;
                ldsm4(smem_u32(&As[row * 40 + col]), a[mt][0], a[mt][1], a[mt][2], a[mt][3]);
            }
#pragma unroll
            for (int ntp = 0; ntp < 2; ntp++) {
                int row = wc * 32 + ntp * 16 + (sub >> 1) * 8 + ri;
                int col = kk + (sub & 1) * 8;
                ldsm4(smem_u32(&Bs[row * 40 + col]),
                      b[ntp * 2][0], b[ntp * 2][1], b[ntp * 2 + 1][0], b[ntp * 2 + 1][1]);
            }
#pragma unroll
            for (int mt = 0; mt < 4; mt++)
#pragma unroll
                for (int nt = 0; nt < 4; nt++)
                    mma16816(acc[mt][nt], a[mt][0], a[mt][1], a[mt][2], a[mt][3],
                             b[nt][0], b[nt][1]);
        }
    }

    const int r0 = lane >> 2, c0 = (lane & 3) * 2;
#pragma unroll
    for (int mt = 0; mt < 4; mt++)
#pragma unroll
        for (int nt = 0; nt < 4; nt++) {
            int n = nblk + wc * 32 + nt * 8 + c0;
#pragma unroll
            for (int half = 0; half < 2; half++) {
                int m = mblk + wr * 64 + mt * 16 + r0 + half * 8;
                float v0 = acc[mt][nt][half * 2 + 0];
                float v1 = acc[mt][nt][half * 2 + 1];
                if (mode == 0) {
                    Cf[(size_t)m * N + n]     = v0 + bias[n];
                    Cf[(size_t)m * N + n + 1] = v1 + bias[n + 1];
                } else {
                    Cb[(size_t)m * N + n]     = __float2bfloat16(v0);
                    Cb[(size_t)m * N + n + 1] = __float2bfloat16(v1);
                }
            }
        }
}

// ---------------- persistent-kernel step GEMM (cp.async pipelined) -----------
// SMEM layout (dynamic): As0 @0, Ws0 @33280, As1 @66560, Ws1 @99840, red @133120
#define SMOFF_AS0 0
#define SMOFF_WS0 33280
#define SMOFF_AS1 66560
#define SMOFF_WS1 99840
#define SMOFF_RED 133120
#define SMEM_RECUR (133120 + 8 * 32 * 33 * 4)   // 166912

__device__ __forceinline__ void issue_chunk(char* smraw, int buf,
    const bf16* Asrc, int ast, const bf16* Wsrc, int wst) {
    bf16* As = (bf16*)(smraw + (buf ? SMOFF_AS1 : SMOFF_AS0));
    bf16* Ws = (bf16*)(smraw + (buf ? SMOFF_WS1 : SMOFF_WS0));
    const int tid = threadIdx.x;
#pragma unroll
    for (int i = 0; i < 8; i++) {
        int v = tid + i * 256;
        int r = v >> 6, c = v & 63;
        cpa16(&As[r * 520 + c * 8], Asrc + (size_t)r * ast + c * 8);
    }
#pragma unroll
    for (int i = 0; i < 8; i++) {
        int v = tid + i * 256;
        int r = v >> 6, c = v & 63;
        cpa16(&Ws[r * 520 + c * 8], Wsrc + (size_t)r * wst + c * 8);
    }
    asm volatile("cp.async.commit_group;");
}

__device__ __forceinline__ void compute_chunk(char* smraw, int buf,
                                              float acc[2][4][4]) {
    bf16* As = (bf16*)(smraw + (buf ? SMOFF_AS1 : SMOFF_AS0));
    bf16* Ws = (bf16*)(smraw + (buf ? SMOFF_WS1 : SMOFF_WS0));
    const int warp = threadIdx.x >> 5, lane = threadIdx.x & 31;
    const int sub = lane >> 3, ri = lane & 7;
#pragma unroll
    for (int kk = 0; kk < 64; kk += 16) {
        int col = (warp << 6) + kk;
        uint32_t a[2][4], b[4][2];
#pragma unroll
        for (int mt = 0; mt < 2; mt++) {
            int row = mt * 16 + (sub & 1) * 8 + ri;
            ldsm4(smem_u32(&As[row * 520 + col + (sub >> 1) * 8]),
                  a[mt][0], a[mt][1], a[mt][2], a[mt][3]);
        }
#pragma unroll
        for (int ntp = 0; ntp < 2; ntp++) {
            int row = ntp * 16 + (sub >> 1) * 8 + ri;
            ldsm4(smem_u32(&Ws[row * 520 + col + (sub & 1) * 8]),
                  b[ntp * 2][0], b[ntp * 2][1], b[ntp * 2 + 1][0], b[ntp * 2 + 1][1]);
        }
#pragma unroll
        for (int mt = 0; mt < 2; mt++)
#pragma unroll
            for (int nt = 0; nt < 4; nt++)
                mma16816(acc[mt][nt], a[mt][0], a[mt][1], a[mt][2], a[mt][3],
                         b[nt][0], b[nt][1]);
    }
}

// C[32, 32cols] = A[32, Kw] @ W[nblk.., Kw]^T; A = [A0 | A1] split at k1.
__device__ void gemm32p(const bf16* __restrict__ A0, int st0,
                        const bf16* __restrict__ A1, int st1,
                        int k1, int Kw,
                        const bf16* __restrict__ W, int nblk,
                        char* smraw, float out[4])
{
    const int tid = threadIdx.x, warp = tid >> 5, lane = tid & 31;
    float acc[2][4][4];
#pragma unroll
    for (int a = 0; a < 2; a++)
#pragma unroll
        for (int b = 0; b < 4; b++)
#pragma unroll
            for (int c = 0; c < 4; c++) acc[a][b][c] = 0.f;

    const int nch = Kw >> 9;
    const bf16* Wb = W + (size_t)nblk * Kw;

    // prologue: chunk 0
    {
        const bf16* Asrc = (0 < k1) ? A0 : A1;
        issue_chunk(smraw, 0, Asrc, (0 < k1) ? st0 : st1, Wb, Kw);
    }
    for (int ch = 0; ch < nch; ch++) {
        __syncthreads();                      // prior compute done
        if (ch + 1 < nch) {
            int k0 = (ch + 1) << 9;
            const bf16* Asrc; int ast;
            if (k0 < k1) { Asrc = A0 + k0; ast = st0; }
            else         { Asrc = A1 + (k0 - k1); ast = st1; }
            issue_chunk(smraw, (ch + 1) & 1, Asrc, ast, Wb + k0, Kw);
            asm volatile("cp.async.wait_group 1;");
        } else {
            asm volatile("cp.async.wait_group 0;");
        }
        __syncthreads();                      // chunk ch visible
        compute_chunk(smraw, ch & 1, acc);
    }

    // cross-warp reduction
    float* red = (float*)(smraw + SMOFF_RED);
    __syncthreads();
    float* rw = red + warp * (32 * 33);
#pragma unroll
    for (int mt = 0; mt < 2; mt++)
#pragma unroll
        for (int nt = 0; nt < 4; nt++) {
            int m = mt * 16 + (lane >> 2);
            int n0 = nt * 8 + (lane & 3) * 2;
            rw[m * 33 + n0]           = acc[mt][nt][0];
            rw[m * 33 + n0 + 1]       = acc[mt][nt][1];
            rw[(m + 8) * 33 + n0]     = acc[mt][nt][2];
            rw[(m + 8) * 33 + n0 + 1] = acc[mt][nt][3];
        }
    __syncthreads();
    int b = tid >> 3, ul = tid & 7;
#pragma unroll
    for (int g = 0; g < 4; g++) {
        float s = 0.f;
#pragma unroll
        for (int w = 0; w < 8; w++) s += red[w * (32 * 33) + b * 33 + ul * 4 + g];
        out[g] = s;
    }
}

// ---------------- attention (device func) ------------------------------------
__device__ void attn_dev(int b, const bf16* __restrict__ h1, char* smraw) {
    float* h1s = (float*)smraw;
    float* sc = h1s + 1024;
    int tid = threadIdx.x;
    for (int u = tid; u < 1024; u += 256) h1s[u] = __bfloat162float(h1[b * 1024 + u]);
    __syncthreads();
    int warp = tid >> 5, lane = tid & 31;
#pragma unroll
    for (int jj = 0; jj < 8; jj++) {
        int j = warp * 8 + jj;
        const uint4* xr = (const uint4*)(g_xa + (size_t)(b * 64 + j) * 1024);
        float s = 0.f;
        for (int k4 = lane; k4 < 128; k4 += 32) {
            uint4 v = xr[k4];
            const __nv_bfloat162* p2 = (const __nv_bfloat162*)&v;
            int base = k4 * 8;
#pragma unroll
            for (int q = 0; q < 4; q++) {
                float2 f = __bfloat1622float2(p2[q]);
                s += h1s[base + q * 2] * f.x + h1s[base + q * 2 + 1] * f.y;
            }
        }
#pragma unroll
        for (int o = 16; o; o >>= 1) s += __shfl_xor_sync(0xffffffffu, s, o);
        if (lane == 0) sc[j] = s + g_badot[b * 64 + j];
    }
    __syncthreads();
    if (warp == 0) {
        float v0 = sc[lane], v1 = sc[lane + 32];
        float m = fmaxf(v0, v1);
#pragma unroll
        for (int o = 16; o; o >>= 1) m = fmaxf(m, __shfl_xor_sync(0xffffffffu, m, o));
        float e0 = expf(v0 - m), e1 = expf(v1 - m);
        float s = e0 + e1;
#pragma unroll
        for (int o = 16; o; o >>= 1) s += __shfl_xor_sync(0xffffffffu, s, o);
        sc[lane] = e0 / s;
        sc[lane + 32] = e1 / s;
    }
    __syncthreads();
    for (int n = tid; n < 1024; n += 256) {
        float a = 0.f;
#pragma unroll 8
        for (int j = 0; j < 64; j++)
            a += sc[j] * __bfloat162float(g_xc[(size_t)(b * 64 + j) * 1024 + n]);
        g_ctxl[b * 1024 + n] = a;
    }
}

// ---------------- persistent recurrence kernel -------------------------------
__global__ void __launch_bounds__(256) k_recur(const float* __restrict__ bl) {
    extern __shared__ char smraw[];
    const int bid = blockIdx.x;
    const int tid = threadIdx.x;

    for (int t = 0; t < NSTEP; t++) {
        const bf16* h0_in  = g_h0buf + (t & 1) * (NB * HH);
        bf16*       h0_out = g_h0buf + ((t + 1) & 1) * (NB * HH);
        const bf16* h1_in  = g_h1buf + (t & 1) * (NB * HH);
        bf16*       h1_out = g_h1buf + ((t + 1) & 1) * (NB * HH);
        const bf16* prev   = g_outs + (size_t)t * (NB * HH);

        // P1: layer-0 gates + cell (K = 2048 = [prev | h0]; e-part from eg)
        if (bid < 128) {
            float s[4];
            gemm32p(prev, 1024, h0_in, 1024, 1024, 2048, g_W0r, bid * 32, smraw, s);
            const float* egp = g_eg + ((size_t)t * 32) * 4096;
            int b = tid >> 3, ul = tid & 7;
            int rn = bid * 32 + ul * 4;
            int u = rn >> 2;
            float ig = s[0] + egp[b * 4096 + rn];
            float fg = s[1] + egp[b * 4096 + rn + 1];
            float gg = s[2] + egp[b * 4096 + rn + 2];
            float og = s[3] + egp[b * 4096 + rn + 3];
            float cn = sigmoidf_(fg) * g_c0[b * 1024 + u] + sigmoidf_(ig) * tanhf(gg);
            g_c0[b * 1024 + u] = cn;
            h0_out[b * 1024 + u] = __float2bfloat16(sigmoidf_(og) * tanhf(cn));
        }
        gbar();

        // P2: layer-1 gates + cell (K = 2048 = [h0_new | h1_prev])
        if (bid < 128) {
            float s[4];
            gemm32p(h0_out, 1024, h1_in, 1024, 1024, 2048, g_W1i, bid * 32, smraw, s);
            int b = tid >> 3, ul = tid & 7;
            int rn = bid * 32 + ul * 4;
            int u = rn >> 2;
            float ig = s[0] + g_b1i[rn];
            float fg = s[1] + g_b1i[rn + 1];
            float gg = s[2] + g_b1i[rn + 2];
            float og = s[3] + g_b1i[rn + 3];
            float cn = sigmoidf_(fg) * g_c1[b * 1024 + u] + sigmoidf_(ig) * tanhf(gg);
            g_c1[b * 1024 + u] = cn;
            h1_out[b * 1024 + u] = __float2bfloat16(sigmoidf_(og) * tanhf(cn));
        }
        gbar();

        // P3: attention (blocks 0-31) || z @ Wlz^T (blocks 32-63)
        if (bid < 32) {
            attn_dev(bid, h1_out, smraw);
        } else if (bid < 64) {
            float s[4];
            gemm32p(h1_out, 1024, h1_out, 1024, 1024, 1024,
                    g_Wlz, (bid - 32) * 32, smraw, s);
            int b = tid >> 3, ul = tid & 7;
            int n = (bid - 32) * 32 + ul * 4;
#pragma unroll
            for (int g = 0; g < 4; g++) g_wl[b * 1024 + n + g] = s[g];
        }
        gbar();

        // P4: out = tanh(wl + bl + ctx) -> outs slot t+1 (bf16)
        if (bid < 32) {
            bf16* outt = g_outs + (size_t)(t + 1) * (NB * HH) + bid * 1024;
            int n = tid * 4;
#pragma unroll
            for (int j = 0; j < 4; j++) {
                float v = g_wl[bid * 1024 + n + j] + bl[n + j] + g_ctxl[bid * 1024 + n + j];
                outt[n + j] = __float2bfloat16(tanhf(v));
            }
        }
        gbar();
    }
}

// ---------------- generator GEMM 256x128 tiles --------------------------------
__global__ void __launch_bounds__(256) k_gen(const bf16* __restrict__ A,
                                             const bf16* __restrict__ W,
                                             const float* __restrict__ bias,
                                             float* __restrict__ out) {
    __shared__ __align__(16) bf16 As[256 * 40];
    __shared__ __align__(16) bf16 Ws[128 * 40];
    const int tid = threadIdx.x, warp = tid >> 5, lane = tid & 31;
    const int wr = warp >> 1, wc = warp & 1;
    const int mblk = blockIdx.y * 256;
    const int nblk = blockIdx.x * 128;
    const int sub = lane >> 3, ri = lane & 7;

    float acc[4][8][4];
#pragma unroll
    for (int a = 0; a < 4; a++)
#pragma unroll
        for (int b = 0; b < 8; b++)
#pragma unroll
            for (int c = 0; c < 4; c++) acc[a][b][c] = 0.f;

    for (int kb = 0; kb < 1024; kb += 32) {
        __syncthreads();
#pragma unroll
        for (int i = 0; i < 6; i++) {
            int v = tid + i * 256;
            if (v < 1024) {
                int m = v >> 2, cv = v & 3;
                *(uint4*)&As[m * 40 + cv * 8] =
                    *(const uint4*)(A + (size_t)(mblk + m) * 1024 + kb + cv * 8);
            } else {
                int u = v - 1024;
                int n = u >> 2, cv = u & 3;
                *(uint4*)&Ws[n * 40 + cv * 8] =
                    *(const uint4*)(W + (size_t)(nblk + n) * 1024 + kb + cv * 8);
            }
        }
        __syncthreads();
#pragma unroll
        for (int kk = 0; kk < 32; kk += 16) {
            uint32_t a[4][4], b[8][2];
#pragma unroll
            for (int mt = 0; mt < 4; mt++) {
                int row = wr * 64 + mt * 16 + (sub & 1) * 8 + ri;
                int col = kk + (sub >> 1) * 8;
                ldsm4(smem_u32(&As[row * 40 + col]), a[mt][0], a[mt][1], a[mt][2], a[mt][3]);
            }
#pragma unroll
            for (int ntp = 0; ntp < 4; ntp++) {
                int row = wc * 64 + ntp * 16 + (sub >> 1) * 8 + ri;
                int col = kk + (sub & 1) * 8;
                ldsm4(smem_u32(&Ws[row * 40 + col]),
                      b[ntp * 2][0], b[ntp * 2][1], b[ntp * 2 + 1][0], b[ntp * 2 + 1][1]);
            }
#pragma unroll
            for (int mt = 0; mt < 4; mt++)
#pragma unroll
                for (int nt = 0; nt < 8; nt++)
                    mma16816(acc[mt][nt], a[mt][0], a[mt][1], a[mt][2], a[mt][3],
                             b[nt][0], b[nt][1]);
        }
    }

    const int r0 = lane >> 2, c0 = (lane & 3) * 2;
#pragma unroll
    for (int mt = 0; mt < 4; mt++)
#pragma unroll
        for (int nt = 0; nt < 8; nt++) {
            int n = nblk + wc * 64 + nt * 8 + c0;
            float bv0 = bias[n], bv1 = bias[n + 1];
#pragma unroll
            for (int half = 0; half < 2; half++) {
                int m = mblk + wr * 64 + mt * 16 + r0 + half * 8;
                if (m < NSTEP * NB) {
                    int t = m >> 5, bb = m & 31;
                    size_t orow = (size_t)(bb * NSTEP + t) * VV;
                    out[orow + n]     = acc[mt][nt][half * 2 + 0] + bv0;
                    out[orow + n + 1] = acc[mt][nt][half * 2 + 1] + bv1;
                }
            }
        }
}

// ---------------- log_softmax (vectorized, in place) --------------------------
__global__ void __launch_bounds__(256) k_lsm(float* __restrict__ out) {
    int row = blockIdx.x;
    float4* p = (float4*)(out + (size_t)row * VV);
    __shared__ float red[256];
    int tid = threadIdx.x;
    float m = -1e30f;
    for (int i = tid; i < 8000; i += 256) {
        float4 v = p[i];
        m = fmaxf(m, fmaxf(fmaxf(v.x, v.y), fmaxf(v.z, v.w)));
    }
    red[tid] = m;
    __syncthreads();
    for (int s = 128; s; s >>= 1) {
        if (tid < s) red[tid] = fmaxf(red[tid], red[tid + s]);
        __syncthreads();
    }
    m = red[0];
    __syncthreads();
    float sum = 0.f;
    for (int i = tid; i < 8000; i += 256) {
        float4 v = p[i];
        sum += expf(v.x - m) + expf(v.y - m) + expf(v.z - m) + expf(v.w - m);
    }
    red[tid] = sum;
    __syncthreads();
    for (int s = 128; s; s >>= 1) {
        if (tid < s) red[tid] += red[tid + s];
        __syncthreads();
    }
    float lse = m + logf(red[0]);
    for (int i = tid; i < 8000; i += 256) {
        float4 v = p[i];
        v.x -= lse; v.y -= lse; v.z -= lse; v.w -= lse;
        p[i] = v;
    }
}

// ---------------- host ---------------------------------------------------------
static void* sym(const void* s) {
    void* p = nullptr;
    cudaGetSymbolAddress(&p, s);
    return p;
}

extern "C" void kernel_launch(void* const* d_in, const int* in_sizes, int n_in,
                              void* d_out, int out_size) {
    const int*   x     = (const int*)d_in[0];
    const float* h0in  = (const float*)d_in[1];
    const float* c0in  = (const float*)d_in[2];
    const float* x_enc = (const float*)d_in[3];
    const float* emb   = (const float*)d_in[4];
    const float* Wih0  = (const float*)d_in[5];
    const float* Whh0  = (const float*)d_in[6];
    const float* bih0  = (const float*)d_in[7];
    const float* bhh0  = (const float*)d_in[8];
    const float* Wih1  = (const float*)d_in[9];
    const float* Whh1  = (const float*)d_in[10];
    const float* bih1  = (const float*)d_in[11];
    const float* bhh1  = (const float*)d_in[12];
    const float* Wa    = (const float*)d_in[13];
    const float* ba    = (const float*)d_in[14];
    const float* Wl    = (const float*)d_in[15];
    const float* bl    = (const float*)d_in[16];
    const float* Wg    = (const float*)d_in[17];
    const float* bg    = (const float*)d_in[18];
    float* out = (float*)d_out;

    bf16*  pW0r = (bf16*)sym(g_W0r);
    bf16*  pW0e = (bf16*)sym(g_W0e);
    bf16*  pW1i = (bf16*)sym(g_W1i);
    bf16*  pWaT = (bf16*)sym(g_WaT);
    bf16*  pWlz = (bf16*)sym(g_Wlz);
    bf16*  pWlc = (bf16*)sym(g_Wlc);
    bf16*  pWg  = (bf16*)sym(g_Wg);
    bf16*  pEs  = (bf16*)sym(g_eseq);
    float* pEg  = (float*)sym(g_eg);
    bf16*  pXe  = (bf16*)sym(g_xe);
    bf16*  pXa  = (bf16*)sym(g_xa);
    bf16*  pXc  = (bf16*)sym(g_xc);
    bf16*  pOuts= (bf16*)sym(g_outs);
    float* pB0i = (float*)sym(g_b0i);
    float* pB1i = (float*)sym(g_b1i);
    float* pBad = (float*)sym(g_badot);

    static bool attr_done = false;
    if (!attr_done) {
        cudaFuncSetAttribute(k_recur, cudaFuncAttributeMaxDynamicSharedMemorySize,
                             SMEM_RECUR);
        attr_done = true;
    }

    // ---- precompute (vectorized conversions + loop-invariant GEMMs) ----
    {
        int n8;
        n8 = 4096 * 256; k_cvt_w0r_i8<<<(n8 + 255) / 256, 256>>>(pW0r, Wih0, Whh0);
        n8 = 4096 * 64;  k_cvt_w0e_i8<<<(n8 + 255) / 256, 256>>>(pW0e, Wih0);
        n8 = 4096 * 256; k_cvt_w1_i8<<<(n8 + 255) / 256, 256>>>(pW1i, Wih1, Whh1);
        k_cvt_T<<<4096, 256>>>(pWaT, Wa);
        n8 = 1024 * 128;
        k_cvt_slice8<<<(n8 + 255) / 256, 256>>>(pWlz, Wl, 2048, 0, 128, n8);
        k_cvt_slice8<<<(n8 + 255) / 256, 256>>>(pWlc, Wl, 2048, 1024, 128, n8);
        n8 = 32000 * 128; k_cvt8<<<(n8 + 255) / 256, 256>>>(pWg, Wg, n8);
        n8 = 2048 * 128;  k_cvt8<<<(n8 + 255) / 256, 256>>>(pXe, x_enc, n8);
        k_addb_i<<<16, 256>>>(pB0i, bih0, bhh0);
        k_addb_i<<<16, 256>>>(pB1i, bih1, bhh1);
        n8 = NSTEP * NB * 64; k_embed8<<<(n8 + 255) / 256, 256>>>(pEs, x, emb);
        k_init<<<128, 256>>>(h0in, c0in);
        k_badot<<<256, 256>>>(ba, x_enc, pBad);
        // eg = eseq @ W0e^T + b0i   [2048, 4096] fp32 (interleaved cols)
        k_gemm_big<<<dim3(32, 16), 256>>>(pEs, pW0e, pB0i, pEg, nullptr, 4096, 512, 0);
        // xa = x_enc @ Wa,  xc = x_enc @ Wlc^T  (bf16)
        k_gemm_big<<<dim3(8, 16), 256>>>(pXe, pWaT, nullptr, nullptr, pXa, 1024, 1024, 1);
        k_gemm_big<<<dim3(8, 16), 256>>>(pXe, pWlc, nullptr, nullptr, pXc, 1024, 1024, 1);
    }

    // ---- full recurrence: ONE persistent kernel ----
    k_recur<<<GRID_P, 256, SMEM_RECUR>>>(bl);

    // ---- generator + log_softmax ----
    k_gen<<<dim3(250, 8), 256>>>(pOuts + NB * HH, pWg, bg, out);
    k_lsm<<<NSTEP * NB, 256>>>(out);

    (void)in_sizes; (void)n_in; (void)out_size;
}

// round 7
// speedup vs baseline: 4.1603x; 1.0755x over previous
#include <cuda_runtime.h>
#include <cuda_bf16.h>
#include <cstdint>

typedef __nv_bfloat16 bf16;

#define NB 32
#define TT 64
#define NSTEP 63
#define HH 1024
#define VV 32000
#define GRID_P 148

// swizzle for 1024-byte-stride rows (32x512 bf16 chunks): XOR row%8 into 16B slot
__device__ __forceinline__ uint32_t SWZ(uint32_t off) {
    return off ^ (((off >> 10) & 7u) << 4);
}

// ---------------- static scratch --------------------------------------------
// W arrays: tile/quarter-chunked + swizzled. tile = 32 rows; quarter = 512 cols.
__device__ __align__(128) bf16 g_W0q[4096 * 2048];  // 128 tiles x 4 q x 32KB
__device__ __align__(128) bf16 g_W1q[4096 * 2048];
__device__ __align__(128) bf16 g_Wlzq[1024 * 1024]; // 32 tiles x 2 q x 32KB
__device__ __align__(128) bf16 g_W0e[4096 * 512];   // interleaved rows, linear
__device__ __align__(128) bf16 g_WaT[1024 * 1024];  // linear
__device__ __align__(128) bf16 g_Wlc[1024 * 1024];  // linear
__device__ __align__(128) bf16 g_Wg [32000 * 1024]; // linear
__device__ __align__(128) bf16 g_eseq[2048 * 512];  // linear
__device__ __align__(128) float g_eg [2048 * 4096]; // e@W0e^T + b0 (interleaved cols)
__device__ __align__(128) bf16 g_xe[2048 * 1024];
__device__ __align__(128) bf16 g_xa[2048 * 1024];
__device__ __align__(128) bf16 g_xc[2048 * 1024];
// outs: 65 slots of 64KB; slot = 2 chunks(q) x (32 b x 512 cols) swizzled; slot0/64 zero
__device__ __align__(128) bf16 g_outs[2080 * 1024];
__device__ float g_b1i[4096];
__device__ float g_b0i[4096];
__device__ __align__(128) bf16 g_h0buf[2 * NB * HH]; // two 64KB chunked+swizzled bufs
__device__ __align__(128) bf16 g_h1buf[2 * NB * HH];
__device__ float g_c0[NB * HH];
__device__ float g_c1[NB * HH];
__device__ float g_ctxl[NB * HH];
__device__ float g_wl[NB * HH];
__device__ float g_badot[2048];
__device__ unsigned long long g_bar_cnt;
__device__ unsigned long long g_bar_gen;

// ---------------- helpers ----------------------------------------------------
__device__ __forceinline__ uint32_t smem_u32(const void* p) {
    return (uint32_t)__cvta_generic_to_shared(p);
}
__device__ __forceinline__ void ldsm4(uint32_t addr, uint32_t& r0, uint32_t& r1,
                                      uint32_t& r2, uint32_t& r3) {
    asm volatile("ldmatrix.sync.aligned.m8n8.x4.shared.b16 {%0,%1,%2,%3}, [%4];"
                 : "=r"(r0), "=r"(r1), "=r"(r2), "=r"(r3) : "r"(addr));
}
__device__ __forceinline__ void mma16816(float* c, uint32_t a0, uint32_t a1,
                                         uint32_t a2, uint32_t a3,
                                         uint32_t b0, uint32_t b1) {
    asm volatile(
        "mma.sync.aligned.m16n8k16.row.col.f32.bf16.bf16.f32 "
        "{%0,%1,%2,%3},{%4,%5,%6,%7},{%8,%9},{%0,%1,%2,%3};"
        : "+f"(c[0]), "+f"(c[1]), "+f"(c[2]), "+f"(c[3])
        : "r"(a0), "r"(a1), "r"(a2), "r"(a3), "r"(b0), "r"(b1));
}
__device__ __forceinline__ float sigmoidf_(float x) { return 1.f / (1.f + expf(-x)); }
__device__ __forceinline__ uint4 pack8(float4 a, float4 b) {
    uint4 o;
    __nv_bfloat162 p;
    p = __floats2bfloat162_rn(a.x, a.y); o.x = *(uint32_t*)&p;
    p = __floats2bfloat162_rn(a.z, a.w); o.y = *(uint32_t*)&p;
    p = __floats2bfloat162_rn(b.x, b.y); o.z = *(uint32_t*)&p;
    p = __floats2bfloat162_rn(b.z, b.w); o.w = *(uint32_t*)&p;
    return o;
}
// --- 1D TMA bulk + mbarrier ---
__device__ __forceinline__ void tma1d(uint32_t dst, const void* src, uint32_t bytes,
                                      uint32_t mbar) {
    asm volatile(
        "cp.async.bulk.shared::cluster.global.mbarrier::complete_tx::bytes "
        "[%0], [%1], %2, [%3];"
        :: "r"(dst), "l"(src), "r"(bytes), "r"(mbar) : "memory");
}
__device__ __forceinline__ void mb_init(uint32_t mbar) {
    asm volatile("mbarrier.init.shared.b64 [%0], 1;" :: "r"(mbar) : "memory");
}
__device__ __forceinline__ void mb_expect(uint32_t mbar, uint32_t tx) {
    asm volatile("mbarrier.arrive.expect_tx.shared.b64 _, [%0], %1;"
                 :: "r"(mbar), "r"(tx) : "memory");
}
__device__ __forceinline__ void mb_wait(uint32_t mbar, int parity) {
    asm volatile(
        "{\n\t.reg .pred P;\n"
        "WL%=:\n\t"
        "mbarrier.try_wait.parity.acquire.cta.shared::cta.b64 P, [%0], %1, 0x989680;\n\t"
        "@P bra WD%=;\n\t"
        "bra WL%=;\n"
        "WD%=:\n\t}"
        :: "r"(mbar), "r"(parity) : "memory");
}
// grid-wide barrier (monotonic counter, graph-replay safe)
__device__ __forceinline__ void gbar() {
    __syncthreads();
    if (threadIdx.x == 0) {
        __threadfence();
        unsigned long long arrive = atomicAdd(&g_bar_cnt, 1ULL);
        unsigned long long target = arrive / GRID_P + 1ULL;
        if ((arrive % GRID_P) == GRID_P - 1) {
            atomicAdd(&g_bar_gen, 1ULL);
        } else {
            unsigned long long g;
            do {
                __nanosleep(32);
                asm volatile("ld.acquire.gpu.global.u64 %0, [%1];"
                             : "=l"(g) : "l"(&g_bar_gen));
            } while (g < target);
        }
        __threadfence();
    }
    __syncthreads();
}

// ---------------- conversion kernels ----------------------------------------
__global__ void k_cvt8(bf16* dst, const float* src, int n8) {
    int i = blockIdx.x * blockDim.x + threadIdx.x;
    if (i < n8) {
        const float4* s = (const float4*)src + (size_t)i * 2;
        ((uint4*)dst)[i] = pack8(s[0], s[1]);
    }
}
// [Wih(cols ihOff..ihOff+1023) | Whh] with rows interleaved 4u+gate, into
// tile/quarter chunks (tile stride 128KB) + SWZ
__global__ void k_cvt_wq(bf16* dst, const float* Wih, int ihStride, int ihOff,
                         const float* Whh) {
    int i = blockIdx.x * blockDim.x + threadIdx.x;   // 4096*256
    if (i >= 4096 * 256) return;
    int rn = i >> 8, c = (i & 255) * 8;
    int srow = (rn & 3) * 1024 + (rn >> 2);
    const float* s = (c < 1024) ? (Wih + (size_t)srow * ihStride + ihOff + c)
                                : (Whh + (size_t)srow * 1024 + (c - 1024));
    uint32_t off = SWZ((uint32_t)((rn & 31) * 1024 + (c & 511) * 2));
    char* d = (char*)dst + (size_t)(rn >> 5) * 131072 + (size_t)(c >> 9) * 32768 + off;
    *(uint4*)d = pack8(((const float4*)s)[0], ((const float4*)s)[1]);
}
// Wl[:, :1024] -> 32 tiles x 2 quarters (tile stride 64KB) + SWZ
__global__ void k_cvt_wlzq(bf16* dst, const float* Wl) {
    int i = blockIdx.x * blockDim.x + threadIdx.x;   // 1024*128
    if (i >= 1024 * 128) return;
    int rn = i >> 7, c = (i & 127) * 8;
    const float* s = Wl + (size_t)rn * 2048 + c;
    uint32_t off = SWZ((uint32_t)((rn & 31) * 1024 + (c & 511) * 2));
    char* d = (char*)dst + (size_t)(rn >> 5) * 65536 + (size_t)(c >> 9) * 32768 + off;
    *(uint4*)d = pack8(((const float4*)s)[0], ((const float4*)s)[1]);
}
__global__ void k_cvt_w0e_i8(bf16* dst, const float* Wih0) {
    int i = blockIdx.x * blockDim.x + threadIdx.x;   // 4096*64
    if (i < 4096 * 64) {
        int rn = i >> 6, c8 = (i & 63) * 8;
        int srow = (rn & 3) * 1024 + (rn >> 2);
        const float* s = Wih0 + (size_t)srow * 1536 + c8;
        ((uint4*)dst)[i] = pack8(((const float4*)s)[0], ((const float4*)s)[1]);
    }
}
__global__ void k_cvt_slice8(bf16* dst, const float* src, int strideS, int off,
                             int w8, int n8) {
    int i = blockIdx.x * blockDim.x + threadIdx.x;
    if (i < n8) {
        int r = i / w8, c8 = (i % w8) * 8;
        const float* s = src + (size_t)r * strideS + off + c8;
        ((uint4*)dst)[i] = pack8(((const float4*)s)[0], ((const float4*)s)[1]);
    }
}
__global__ void k_cvt_T(bf16* dst, const float* src) {
    int i = blockIdx.x * blockDim.x + threadIdx.x;
    if (i < 1024 * 1024) {
        int n = i >> 10, h = i & 1023;
        dst[i] = __float2bfloat16(src[h * 1024 + n]);
    }
}
__global__ void k_addb_i(float* dst, const float* a, const float* b) {
    int i = blockIdx.x * blockDim.x + threadIdx.x;
    if (i < 4096) {
        int u = i >> 2, g = i & 3;
        dst[i] = a[g * 1024 + u] + b[g * 1024 + u];
    }
}
__global__ void k_embed8(bf16* eseq, const int* x, const float* emb) {
    int i = blockIdx.x * blockDim.x + threadIdx.x;
    if (i < NSTEP * NB * 64) {
        int c8 = (i & 63) * 8;
        int m = i >> 6;
        int b = m & 31, t = m >> 5;
        int tok = x[b * TT + t];
        const float* s = emb + (size_t)tok * 512 + c8;
        ((uint4*)eseq)[i] = pack8(((const float4*)s)[0], ((const float4*)s)[1]);
    }
}
__global__ void k_init(const float* h0in, const float* c0in) {
    int i = blockIdx.x * blockDim.x + threadIdx.x;
    if (i < NB * HH) {
        int b = i >> 10, u = i & 1023;
        uint32_t off = (uint32_t)(u >> 9) * 32768 + SWZ((uint32_t)(b * 1024 + (u & 511) * 2));
        *(bf16*)((char*)g_h0buf + off) = __float2bfloat16(h0in[i]);
        *(bf16*)((char*)g_h1buf + off) = __float2bfloat16(h0in[NB * HH + i]);
        g_c0[i] = c0in[i];
        g_c1[i] = c0in[NB * HH + i];
    }
}
__global__ void k_badot(const float* ba, const float* x_enc, float* badot) {
    int warp = threadIdx.x >> 5, lane = threadIdx.x & 31;
    int row = blockIdx.x * 8 + warp;
    const float* xr = x_enc + (size_t)row * 1024;
    float s = 0.f;
    for (int h = lane; h < 1024; h += 32) s += ba[h] * xr[h];
#pragma unroll
    for (int o = 16; o; o >>= 1) s += __shfl_xor_sync(0xffffffffu, s, o);
    if (lane == 0) badot[row] = s;
}

// ---------------- generic 128x128 GEMM (precompute) --------------------------
__global__ void __launch_bounds__(256) k_gemm_big(
    const bf16* __restrict__ A, const bf16* __restrict__ W,
    const float* __restrict__ bias, float* __restrict__ Cf, bf16* __restrict__ Cb,
    int N, int K, int mode)
{
    __shared__ __align__(16) bf16 As[128 * 40];
    __shared__ __align__(16) bf16 Bs[128 * 40];
    const int tid = threadIdx.x, warp = tid >> 5, lane = tid & 31;
    const int wr = warp >> 2, wc = warp & 3;
    const int mblk = blockIdx.y * 128;
    const int nblk = blockIdx.x * 128;
    const int sub = lane >> 3, ri = lane & 7;

    float acc[4][4][4];
#pragma unroll
    for (int a = 0; a < 4; a++)
#pragma unroll
        for (int b = 0; b < 4; b++)
#pragma unroll
            for (int c = 0; c < 4; c++) acc[a][b][c] = 0.f;

    for (int kb = 0; kb < K; kb += 32) {
        __syncthreads();
#pragma unroll
        for (int i = 0; i < 4; i++) {
            int v = tid + i * 256;
            if (v < 512) {
                int m = v >> 2, cv = v & 3;
                *(uint4*)&As[m * 40 + cv * 8] =
                    *(const uint4*)(A + (size_t)(mblk + m) * K + kb + cv * 8);
            } else {
                int u = v - 512;
                int n = u >> 2, cv = u & 3;
                *(uint4*)&Bs[n * 40 + cv * 8] =
                    *(const uint4*)(W + (size_t)(nblk + n) * K + kb + cv * 8);
            }
        }
        __syncthreads();
#pragma unroll
        for (int kk = 0; kk < 32; kk += 16) {
            uint32_t a[4][4], b[4][2];
#pragma unroll
            for (int mt = 0; mt < 4; mt++) {
                int row = wr * 64 + mt * 16 + (sub & 1) * 8 + ri;
                int col = kk + (sub >> 1) * 8;
                ldsm4(smem_u32(&As[row * 40 + col]), a[mt][0], a[mt][1], a[mt][2], a[mt][3]);
            }
#pragma unroll
            for (int ntp = 0; ntp < 2; ntp++) {
                int row = wc * 32 + ntp * 16 + (sub >> 1) * 8 + ri;
                int col = kk + (sub & 1) * 8;
                ldsm4(smem_u32(&Bs[row * 40 + col]),
                      b[ntp * 2][0], b[ntp * 2][1], b[ntp * 2 + 1][0], b[ntp * 2 + 1][1]);
            }
#pragma unroll
            for (int mt = 0; mt < 4; mt++)
#pragma unroll
                for (int nt = 0; nt < 4; nt++)
                    mma16816(acc[mt][nt], a[mt][0], a[mt][1], a[mt][2], a[mt][3],
                             b[nt][0], b[nt][1]);
        }
    }

    const int r0 = lane >> 2, c0 = (lane & 3) * 2;
#pragma unroll
    for (int mt = 0; mt < 4; mt++)
#pragma unroll
        for (int nt = 0; nt < 4; nt++) {
            int n = nblk + wc * 32 + nt * 8 + c0;
#pragma unroll
            for (int half = 0; half < 2; half++) {
                int m = mblk + wr * 64 + mt * 16 + r0 + half * 8;
                float v0 = acc[mt][nt][half * 2 + 0];
                float v1 = acc[mt][nt][half * 2 + 1];
                if (mode == 0) {
                    Cf[(size_t)m * N + n]     = v0 + bias[n];
                    Cf[(size_t)m * N + n + 1] = v1 + bias[n + 1];
                } else {
                    Cb[(size_t)m * N + n]     = __float2bfloat16(v0);
                    Cb[(size_t)m * N + n + 1] = __float2bfloat16(v1);
                }
            }
        }
}

// ---------------- persistent recurrence: TMA-fed step GEMM -------------------
// smem: A0 @0, W0 @32768, A1 @65536, W1 @98304, red @131072 (33792), mb @164864
#define SMOFF_A0  0
#define SMOFF_W0  32768
#define SMOFF_A1  65536
#define SMOFF_W1  98304
#define SMOFF_RED 131072
#define SMOFF_MB  164864
#define SMEM_RECUR 164896

__device__ __forceinline__ void comp_chunk(uint32_t aB, uint32_t wB,
                                           float acc[2][4][4]) {
    const int warp = threadIdx.x >> 5, lane = threadIdx.x & 31;
    const int sub = lane >> 3, ri = lane & 7;
#pragma unroll
    for (int kk = 0; kk < 64; kk += 16) {
        int col = (warp << 6) + kk;
        uint32_t a[2][4], b[4][2];
#pragma unroll
        for (int mt = 0; mt < 2; mt++) {
            uint32_t off = (uint32_t)((mt * 16 + (sub & 1) * 8 + ri) * 1024 +
                                      (col + (sub >> 1) * 8) * 2);
            ldsm4(aB + SWZ(off), a[mt][0], a[mt][1], a[mt][2], a[mt][3]);
        }
#pragma unroll
        for (int ntp = 0; ntp < 2; ntp++) {
            uint32_t off = (uint32_t)((ntp * 16 + (sub >> 1) * 8 + ri) * 1024 +
                                      (col + (sub & 1) * 8) * 2);
            ldsm4(wB + SWZ(off), b[ntp * 2][0], b[ntp * 2][1],
                  b[ntp * 2 + 1][0], b[ntp * 2 + 1][1]);
        }
#pragma unroll
        for (int mt = 0; mt < 2; mt++)
#pragma unroll
            for (int nt = 0; nt < 4; nt++)
                mma16816(acc[mt][nt], a[mt][0], a[mt][1], a[mt][2], a[mt][3],
                         b[nt][0], b[nt][1]);
    }
}

__device__ __forceinline__ void reduce32(char* sm, float acc[2][4][4], float out[4]) {
    float* red = (float*)(sm + SMOFF_RED);
    const int tid = threadIdx.x, warp = tid >> 5, lane = tid & 31;
    __syncthreads();
    float* rw = red + warp * (32 * 33);
#pragma unroll
    for (int mt = 0; mt < 2; mt++)
#pragma unroll
        for (int nt = 0; nt < 4; nt++) {
            int m = mt * 16 + (lane >> 2);
            int n0 = nt * 8 + (lane & 3) * 2;
            rw[m * 33 + n0]           = acc[mt][nt][0];
            rw[m * 33 + n0 + 1]       = acc[mt][nt][1];
            rw[(m + 8) * 33 + n0]     = acc[mt][nt][2];
            rw[(m + 8) * 33 + n0 + 1] = acc[mt][nt][3];
        }
    __syncthreads();
    int b = tid >> 3, ul = tid & 7;
#pragma unroll
    for (int g = 0; g < 4; g++) {
        float s = 0.f;
#pragma unroll
        for (int w = 0; w < 8; w++) s += red[w * (32 * 33) + b * 33 + ul * 4 + g];
        out[g] = s;
    }
}

// C[32,32] = A[32, nch*512] @ Wtile^T. ach[i] = i-th 32KB A chunk; wtile chunks
// at wtile + q*32768. Double-buffered TMA pipeline.
__device__ void gemm32t(const char* a0, const char* a1, const char* a2, const char* a3,
                        const char* wtile, int nch, char* sm, int2& ph, float out[4]) {
    const int tid = threadIdx.x;
    const char* ach[4] = {a0, a1, a2, a3};
    uint32_t smb = smem_u32(sm);
    uint32_t mb0 = smb + SMOFF_MB, mb1 = smb + SMOFF_MB + 8;
    float acc[2][4][4];
#pragma unroll
    for (int a = 0; a < 2; a++)
#pragma unroll
        for (int b = 0; b < 4; b++)
#pragma unroll
            for (int c = 0; c < 4; c++) acc[a][b][c] = 0.f;

    if (tid == 0) {
        mb_expect(mb0, 65536);
        tma1d(smb + SMOFF_A0, ach[0], 32768, mb0);
        tma1d(smb + SMOFF_W0, wtile, 32768, mb0);
    }
    for (int ch = 0; ch < nch; ch++) {
        int buf = ch & 1;
        if (ch + 1 < nch && tid == 0) {
            uint32_t mbn = buf ? mb0 : mb1;
            mb_expect(mbn, 65536);
            tma1d(smb + (buf ? SMOFF_A0 : SMOFF_A1), ach[ch + 1], 32768, mbn);
            tma1d(smb + (buf ? SMOFF_W0 : SMOFF_W1),
                  wtile + (size_t)(ch + 1) * 32768, 32768, mbn);
        }
        if (buf) { mb_wait(mb1, ph.y); ph.y ^= 1; }
        else     { mb_wait(mb0, ph.x); ph.x ^= 1; }
        comp_chunk(smb + (buf ? SMOFF_A1 : SMOFF_A0),
                   smb + (buf ? SMOFF_W1 : SMOFF_W0), acc);
        __syncthreads();
    }
    reduce32(sm, acc, out);
}

// ---------------- attention (device func) ------------------------------------
__device__ void attn_dev(int b, const char* __restrict__ h1base, char* smraw) {
    float* h1s = (float*)(smraw + SMOFF_RED);          // reuse red region
    float* sc = h1s + 1024;
    int tid = threadIdx.x;
    for (int u = tid; u < 1024; u += 256) {
        uint32_t off = (uint32_t)(u >> 9) * 32768 + SWZ((uint32_t)(b * 1024 + (u & 511) * 2));
        h1s[u] = __bfloat162float(*(const bf16*)(h1base + off));
    }
    __syncthreads();
    int warp = tid >> 5, lane = tid & 31;
#pragma unroll
    for (int jj = 0; jj < 8; jj++) {
        int j = warp * 8 + jj;
        const uint4* xr = (const uint4*)(g_xa + (size_t)(b * 64 + j) * 1024);
        float s = 0.f;
        for (int k4 = lane; k4 < 128; k4 += 32) {
            uint4 v = xr[k4];
            const __nv_bfloat162* p2 = (const __nv_bfloat162*)&v;
            int base = k4 * 8;
#pragma unroll
            for (int q = 0; q < 4; q++) {
                float2 f = __bfloat1622float2(p2[q]);
                s += h1s[base + q * 2] * f.x + h1s[base + q * 2 + 1] * f.y;
            }
        }
#pragma unroll
        for (int o = 16; o; o >>= 1) s += __shfl_xor_sync(0xffffffffu, s, o);
        if (lane == 0) sc[j] = s + g_badot[b * 64 + j];
    }
    __syncthreads();
    if (warp == 0) {
        float v0 = sc[lane], v1 = sc[lane + 32];
        float m = fmaxf(v0, v1);
#pragma unroll
        for (int o = 16; o; o >>= 1) m = fmaxf(m, __shfl_xor_sync(0xffffffffu, m, o));
        float e0 = expf(v0 - m), e1 = expf(v1 - m);
        float s = e0 + e1;
#pragma unroll
        for (int o = 16; o; o >>= 1) s += __shfl_xor_sync(0xffffffffu, s, o);
        sc[lane] = e0 / s;
        sc[lane + 32] = e1 / s;
    }
    __syncthreads();
    for (int n = tid; n < 1024; n += 256) {
        float a = 0.f;
#pragma unroll 8
        for (int j = 0; j < 64; j++)
            a += sc[j] * __bfloat162float(g_xc[(size_t)(b * 64 + j) * 1024 + n]);
        g_ctxl[b * 1024 + n] = a;
    }
}

// ---------------- persistent recurrence kernel -------------------------------
__global__ void __launch_bounds__(256) k_recur(const float* __restrict__ bl) {
    extern __shared__ __align__(128) char smraw[];
    const int bid = blockIdx.x;
    const int tid = threadIdx.x;

    if (tid == 0) {
        mb_init(smem_u32(smraw) + SMOFF_MB);
        mb_init(smem_u32(smraw) + SMOFF_MB + 8);
    }
    asm volatile("fence.proxy.async.shared::cta;" ::: "memory");
    __syncthreads();
    int2 ph = make_int2(0, 0);

    for (int t = 0; t < NSTEP; t++) {
        const char* h0_in  = (const char*)g_h0buf + (t & 1) * 65536;
        char*       h0_out = (char*)g_h0buf + ((t + 1) & 1) * 65536;
        const char* h1_in  = (const char*)g_h1buf + (t & 1) * 65536;
        char*       h1_out = (char*)g_h1buf + ((t + 1) & 1) * 65536;
        const char* prev   = (const char*)g_outs + (size_t)t * 65536;

        // P1: layer-0 gates + cell (K=2048 = [prev | h0_in]; e-part from eg)
        if (bid < 128) {
            float s[4];
            gemm32t(prev, prev + 32768, h0_in, h0_in + 32768,
                    (const char*)g_W0q + (size_t)bid * 131072, 4, smraw, ph, s);
            const float* egp = g_eg + (size_t)t * 32 * 4096;
            int b = tid >> 3, ul = tid & 7;
            int rn = bid * 32 + ul * 4;
            int u = rn >> 2;
            float ig = s[0] + egp[b * 4096 + rn];
            float fg = s[1] + egp[b * 4096 + rn + 1];
            float gg = s[2] + egp[b * 4096 + rn + 2];
            float og = s[3] + egp[b * 4096 + rn + 3];
            float cn = sigmoidf_(fg) * g_c0[b * 1024 + u] + sigmoidf_(ig) * tanhf(gg);
            g_c0[b * 1024 + u] = cn;
            uint32_t off = (uint32_t)(u >> 9) * 32768 + SWZ((uint32_t)(b * 1024 + (u & 511) * 2));
            *(bf16*)(h0_out + off) = __float2bfloat16(sigmoidf_(og) * tanhf(cn));
        }
        gbar();

        // P2: layer-1 gates + cell (K=2048 = [h0_new | h1_prev])
        if (bid < 128) {
            float s[4];
            gemm32t(h0_out, h0_out + 32768, h1_in, h1_in + 32768,
                    (const char*)g_W1q + (size_t)bid * 131072, 4, smraw, ph, s);
            int b = tid >> 3, ul = tid & 7;
            int rn = bid * 32 + ul * 4;
            int u = rn >> 2;
            float ig = s[0] + g_b1i[rn];
            float fg = s[1] + g_b1i[rn + 1];
            float gg = s[2] + g_b1i[rn + 2];
            float og = s[3] + g_b1i[rn + 3];
            float cn = sigmoidf_(fg) * g_c1[b * 1024 + u] + sigmoidf_(ig) * tanhf(gg);
            g_c1[b * 1024 + u] = cn;
            uint32_t off = (uint32_t)(u >> 9) * 32768 + SWZ((uint32_t)(b * 1024 + (u & 511) * 2));
            *(bf16*)(h1_out + off) = __float2bfloat16(sigmoidf_(og) * tanhf(cn));
        }
        gbar();

        // P3: attention (blocks 0-31) || z @ Wlz^T (blocks 32-63)
        if (bid < 32) {
            attn_dev(bid, h1_out, smraw);
        } else if (bid < 64) {
            float s[4];
            gemm32t(h1_out, h1_out + 32768, h1_out, h1_out,
                    (const char*)g_Wlzq + (size_t)(bid - 32) * 65536, 2, smraw, ph, s);
            int b = tid >> 3, ul = tid & 7;
            int n = (bid - 32) * 32 + ul * 4;
#pragma unroll
            for (int g = 0; g < 4; g++) g_wl[b * 1024 + n + g] = s[g];
        }
        gbar();

        // P4: out = tanh(wl + bl + ctx) -> outs slot t+1 (chunked + SWZ)
        if (bid < 32) {
            char* outt = (char*)g_outs + (size_t)(t + 1) * 65536;
#pragma unroll
            for (int j = 0; j < 4; j++) {
                int n = tid * 4 + j;
                float v = g_wl[bid * 1024 + n] + bl[n] + g_ctxl[bid * 1024 + n];
                uint32_t off = (uint32_t)(n >> 9) * 32768 +
                               SWZ((uint32_t)(bid * 1024 + (n & 511) * 2));
                *(bf16*)(outt + off) = __float2bfloat16(tanhf(v));
            }
        }
        gbar();
    }
}

// ---------------- generator GEMM 256x128 tiles (A from chunked outs) ----------
__global__ void __launch_bounds__(256) k_gen(const bf16* __restrict__ W,
                                             const float* __restrict__ bias,
                                             float* __restrict__ out) {
    __shared__ __align__(16) bf16 As[256 * 40];
    __shared__ __align__(16) bf16 Ws[128 * 40];
    const int tid = threadIdx.x, warp = tid >> 5, lane = tid & 31;
    const int wr = warp >> 1, wc = warp & 1;
    const int mblk = blockIdx.y * 256;
    const int nblk = blockIdx.x * 128;
    const int sub = lane >> 3, ri = lane & 7;

    float acc[4][8][4];
#pragma unroll
    for (int a = 0; a < 4; a++)
#pragma unroll
        for (int b = 0; b < 8; b++)
#pragma unroll
            for (int c = 0; c < 4; c++) acc[a][b][c] = 0.f;

    for (int kb = 0; kb < 1024; kb += 32) {
        __syncthreads();
#pragma unroll
        for (int i = 0; i < 6; i++) {
            int v = tid + i * 256;
            if (v < 1024) {
                int m = v >> 2, cv = v & 3;
                int gm = mblk + m;                  // global row (t*32+b), slot gm>>5 + 1
                int col = kb + cv * 8;
                size_t byteoff = (size_t)((gm >> 5) + 1) * 65536 +
                                 (size_t)(col >> 9) * 32768 +
                                 SWZ((uint32_t)((gm & 31) * 1024 + (col & 511) * 2));
                *(uint4*)&As[m * 40 + cv * 8] = *(const uint4*)((const char*)g_outs + byteoff);
            } else {
                int u = v - 1024;
                int n = u >> 2, cv = u & 3;
                *(uint4*)&Ws[n * 40 + cv * 8] =
                    *(const uint4*)(W + (size_t)(nblk + n) * 1024 + kb + cv * 8);
            }
        }
        __syncthreads();
#pragma unroll
        for (int kk = 0; kk < 32; kk += 16) {
            uint32_t a[4][4], b[8][2];
#pragma unroll
            for (int mt = 0; mt < 4; mt++) {
                int row = wr * 64 + mt * 16 + (sub & 1) * 8 + ri;
                int col = kk + (sub >> 1) * 8;
                ldsm4(smem_u32(&As[row * 40 + col]), a[mt][0], a[mt][1], a[mt][2], a[mt][3]);
            }
#pragma unroll
            for (int ntp = 0; ntp < 4; ntp++) {
                int row = wc * 64 + ntp * 16 + (sub >> 1) * 8 + ri;
                int col = kk + (sub & 1) * 8;
                ldsm4(smem_u32(&Ws[row * 40 + col]),
                      b[ntp * 2][0], b[ntp * 2][1], b[ntp * 2 + 1][0], b[ntp * 2 + 1][1]);
            }
#pragma unroll
            for (int mt = 0; mt < 4; mt++)
#pragma unroll
                for (int nt = 0; nt < 8; nt++)
                    mma16816(acc[mt][nt], a[mt][0], a[mt][1], a[mt][2], a[mt][3],
                             b[nt][0], b[nt][1]);
        }
    }

    const int r0 = lane >> 2, c0 = (lane & 3) * 2;
#pragma unroll
    for (int mt = 0; mt < 4; mt++)
#pragma unroll
        for (int nt = 0; nt < 8; nt++) {
            int n = nblk + wc * 64 + nt * 8 + c0;
            float bv0 = bias[n], bv1 = bias[n + 1];
#pragma unroll
            for (int half = 0; half < 2; half++) {
                int m = mblk + wr * 64 + mt * 16 + r0 + half * 8;
                if (m < NSTEP * NB) {
                    int t = m >> 5, bb = m & 31;
                    size_t orow = (size_t)(bb * NSTEP + t) * VV;
                    out[orow + n]     = acc[mt][nt][half * 2 + 0] + bv0;
                    out[orow + n + 1] = acc[mt][nt][half * 2 + 1] + bv1;
                }
            }
        }
}

// ---------------- log_softmax (vectorized, in place) --------------------------
__global__ void __launch_bounds__(256) k_lsm(float* __restrict__ out) {
    int row = blockIdx.x;
    float4* p = (float4*)(out + (size_t)row * VV);
    __shared__ float red[256];
    int tid = threadIdx.x;
    float m = -1e30f;
    for (int i = tid; i < 8000; i += 256) {
        float4 v = p[i];
        m = fmaxf(m, fmaxf(fmaxf(v.x, v.y), fmaxf(v.z, v.w)));
    }
    red[tid] = m;
    __syncthreads();
    for (int s = 128; s; s >>= 1) {
        if (tid < s) red[tid] = fmaxf(red[tid], red[tid + s]);
        __syncthreads();
    }
    m = red[0];
    __syncthreads();
    float sum = 0.f;
    for (int i = tid; i < 8000; i += 256) {
        float4 v = p[i];
        sum += expf(v.x - m) + expf(v.y - m) + expf(v.z - m) + expf(v.w - m);
    }
    red[tid] = sum;
    __syncthreads();
    for (int s = 128; s; s >>= 1) {
        if (tid < s) red[tid] += red[tid + s];
        __syncthreads();
    }
    float lse = m + logf(red[0]);
    for (int i = tid; i < 8000; i += 256) {
        float4 v = p[i];
        v.x -= lse; v.y -= lse; v.z -= lse; v.w -= lse;
        p[i] = v;
    }
}

// ---------------- host ---------------------------------------------------------
static void* sym(const void* s) {
    void* p = nullptr;
    cudaGetSymbolAddress(&p, s);
    return p;
}

extern "C" void kernel_launch(void* const* d_in, const int* in_sizes, int n_in,
                              void* d_out, int out_size) {
    const int*   x     = (const int*)d_in[0];
    const float* h0in  = (const float*)d_in[1];
    const float* c0in  = (const float*)d_in[2];
    const float* x_enc = (const float*)d_in[3];
    const float* emb   = (const float*)d_in[4];
    const float* Wih0  = (const float*)d_in[5];
    const float* Whh0  = (const float*)d_in[6];
    const float* bih0  = (const float*)d_in[7];
    const float* bhh0  = (const float*)d_in[8];
    const float* Wih1  = (const float*)d_in[9];
    const float* Whh1  = (const float*)d_in[10];
    const float* bih1  = (const float*)d_in[11];
    const float* bhh1  = (const float*)d_in[12];
    const float* Wa    = (const float*)d_in[13];
    const float* ba    = (const float*)d_in[14];
    const float* Wl    = (const float*)d_in[15];
    const float* bl    = (const float*)d_in[16];
    const float* Wg    = (const float*)d_in[17];
    const float* bg    = (const float*)d_in[18];
    float* out = (float*)d_out;

    bf16*  pW0q = (bf16*)sym(g_W0q);
    bf16*  pW1q = (bf16*)sym(g_W1q);
    bf16*  pWlzq= (bf16*)sym(g_Wlzq);
    bf16*  pW0e = (bf16*)sym(g_W0e);
    bf16*  pWaT = (bf16*)sym(g_WaT);
    bf16*  pWlc = (bf16*)sym(g_Wlc);
    bf16*  pWg  = (bf16*)sym(g_Wg);
    bf16*  pEs  = (bf16*)sym(g_eseq);
    float* pEg  = (float*)sym(g_eg);
    bf16*  pXe  = (bf16*)sym(g_xe);
    bf16*  pXa  = (bf16*)sym(g_xa);
    bf16*  pXc  = (bf16*)sym(g_xc);
    float* pB0i = (float*)sym(g_b0i);
    float* pB1i = (float*)sym(g_b1i);
    float* pBad = (float*)sym(g_badot);

    static bool attr_done = false;
    if (!attr_done) {
        cudaFuncSetAttribute(k_recur, cudaFuncAttributeMaxDynamicSharedMemorySize,
                             SMEM_RECUR);
        attr_done = true;
    }

    // ---- precompute ----
    {
        int n;
        n = 4096 * 256; k_cvt_wq<<<(n + 255) / 256, 256>>>(pW0q, Wih0, 1536, 512, Whh0);
        n = 4096 * 256; k_cvt_wq<<<(n + 255) / 256, 256>>>(pW1q, Wih1, 1024, 0, Whh1);
        n = 1024 * 128; k_cvt_wlzq<<<(n + 255) / 256, 256>>>(pWlzq, Wl);
        n = 4096 * 64;  k_cvt_w0e_i8<<<(n + 255) / 256, 256>>>(pW0e, Wih0);
        k_cvt_T<<<4096, 256>>>(pWaT, Wa);
        n = 1024 * 128; k_cvt_slice8<<<(n + 255) / 256, 256>>>(pWlc, Wl, 2048, 1024, 128, n);
        n = 32000 * 128; k_cvt8<<<(n + 255) / 256, 256>>>(pWg, Wg, n);
        n = 2048 * 128;  k_cvt8<<<(n + 255) / 256, 256>>>(pXe, x_enc, n);
        k_addb_i<<<16, 256>>>(pB0i, bih0, bhh0);
        k_addb_i<<<16, 256>>>(pB1i, bih1, bhh1);
        n = NSTEP * NB * 64; k_embed8<<<(n + 255) / 256, 256>>>(pEs, x, emb);
        k_init<<<128, 256>>>(h0in, c0in);
        k_badot<<<256, 256>>>(ba, x_enc, pBad);
        // eg = eseq @ W0e^T + b0i   [2048, 4096] fp32 (interleaved cols)
        k_gemm_big<<<dim3(32, 16), 256>>>(pEs, pW0e, pB0i, pEg, nullptr, 4096, 512, 0);
        // xa = x_enc @ Wa,  xc = x_enc @ Wlc^T  (bf16, linear)
        k_gemm_big<<<dim3(8, 16), 256>>>(pXe, pWaT, nullptr, nullptr, pXa, 1024, 1024, 1);
        k_gemm_big<<<dim3(8, 16), 256>>>(pXe, pWlc, nullptr, nullptr, pXc, 1024, 1024, 1);
    }

    // ---- full recurrence: ONE persistent kernel (TMA-fed) ----
    k_recur<<<GRID_P, 256, SMEM_RECUR>>>(bl);

    // ---- generator + log_softmax ----
    k_gen<<<dim3(250, 8), 256>>>(pWg, bg, out);
    k_lsm<<<NSTEP * NB, 256>>>(out);

    (void)in_sizes; (void)n_in; (void)out_size;
}